// round 12
// baseline (speedup 1.0000x reference)
#include <cuda_runtime.h>
#include <cuda_bf16.h>
#include <cuda_fp16.h>
#include <cstdint>

#define NUM_B 2
#define SEQ   2048
#define DIM   1024
#define NH    16
#define HD    64
#define M_ROWS (NUM_B*SEQ)
#define N_QKV  (3*DIM)
#define KDIM   DIM
#define NCH    (KDIM/32)

#define LOG2E 1.4426950408889634f
#define C2LE  2.8853900817779268f

// Scratch
__device__ float g_v  [(size_t)NUM_B*NH*SEQ*HD];
// bf16 hi/lo fragment-packed GEMM operands
__device__ uint4 g_xp  [(size_t)M_ROWS*256];
__device__ uint4 g_attp[(size_t)M_ROWS*256];
__device__ uint4 g_wqp [(size_t)N_QKV*256];
__device__ uint4 g_wop [(size_t)DIM*256];
// flash operands (q/k packed directly by qkv epilogue)
__device__ uint4    g_qpb[(size_t)NUM_B*NH*SEQ*16];
__device__ uint4    g_kqb[(size_t)NUM_B*NH*SEQ*16];
__device__ uint32_t g_vph[(size_t)NUM_B*NH*SEQ*32];
__device__ float    g_ksq[(size_t)NUM_B*NH*SEQ];

// ---------------------------------------------------------------------------
// Helpers
// ---------------------------------------------------------------------------
__device__ __forceinline__ float ex2f(float x) {
    float r;
    asm("ex2.approx.f32 %0, %1;" : "=f"(r) : "f"(x));
    return r;
}
__device__ __forceinline__ void bsplit(float x, float& h, float& l) {
    h = __bfloat162float(__float2bfloat16_rn(x));
    l = x - h;
}
__device__ __forceinline__ uint32_t bpack(float a, float b) {
    __nv_bfloat162 t = __floats2bfloat162_rn(a, b);
    return *(uint32_t*)&t;
}
__device__ __forceinline__ uint32_t hpack(float a, float b) {
    __half2 t = __floats2half2_rn(a, b);
    return *(uint32_t*)&t;
}
__device__ __forceinline__ void mma_bf16(float* d,
                                         uint32_t a0, uint32_t a1, uint32_t a2, uint32_t a3,
                                         uint32_t b0, uint32_t b1) {
    asm volatile(
        "mma.sync.aligned.m16n8k16.row.col.f32.bf16.bf16.f32 "
        "{%0,%1,%2,%3}, {%4,%5,%6,%7}, {%8,%9}, {%0,%1,%2,%3};"
        : "+f"(d[0]), "+f"(d[1]), "+f"(d[2]), "+f"(d[3])
        : "r"(a0), "r"(a1), "r"(a2), "r"(a3), "r"(b0), "r"(b1));
}
__device__ __forceinline__ void mma_f16(float* d,
                                        uint32_t a0, uint32_t a1, uint32_t a2, uint32_t a3,
                                        uint32_t b0, uint32_t b1) {
    asm volatile(
        "mma.sync.aligned.m16n8k16.row.col.f32.f16.f16.f32 "
        "{%0,%1,%2,%3}, {%4,%5,%6,%7}, {%8,%9}, {%0,%1,%2,%3};"
        : "+f"(d[0]), "+f"(d[1]), "+f"(d[2]), "+f"(d[3])
        : "r"(a0), "r"(a1), "r"(a2), "r"(a3), "r"(b0), "r"(b1));
}
#define U(x) __float_as_uint(x)
#define CP16(dst, src) \
    asm volatile("cp.async.cg.shared.global [%0], [%1], 16;" :: "r"(dst), "l"(src))
#define CP_COMMIT() asm volatile("cp.async.commit_group;" ::: "memory")
#define CP_WAIT1()  asm volatile("cp.async.wait_group 1;" ::: "memory")
#define CP_WAIT0()  asm volatile("cp.async.wait_group 0;" ::: "memory")
__device__ __forceinline__ uint32_t smem_u32(const void* p) {
    uint32_t a;
    asm("{ .reg .u64 t; cvta.to.shared.u64 t, %1; cvt.u32.u64 %0, t; }"
        : "=r"(a) : "l"(p));
    return a;
}

// ---------------------------------------------------------------------------
// pack_w / pack_x (unchanged)
// ---------------------------------------------------------------------------
__global__ __launch_bounds__(256) void pack_w(const float* __restrict__ W,
                                              uint4* __restrict__ outp, int N) {
    __shared__ float Sw[32 * 136];
    const int t = threadIdx.x;
    const int n0 = blockIdx.x * 128, k0 = blockIdx.y * 32;
    #pragma unroll
    for (int i = 0; i < 4; i++) {
        const int idx = t + i * 256;
        const int kr = idx >> 5, c4 = (idx & 31) * 4;
        *(float4*)&Sw[kr * 136 + c4] =
            *(const float4*)(W + (size_t)(k0 + kr) * N + n0 + c4);
    }
    __syncthreads();
    const size_t ob = ((size_t)blockIdx.x * NCH + blockIdx.y) * 8 * 128;
    #pragma unroll
    for (int i = 0; i < 4; i++) {
        const int idx = t + i * 256;
        const int s = idx >> 7, r = idx & 127;
        const int c0 = (s >> 2) * 16 + 2 * (s & 3), c8 = c0 + 8;
        float h0, l0, h1, l1, h2, l2, h3, l3;
        bsplit(Sw[(c0    ) * 136 + r], h0, l0);
        bsplit(Sw[(c0 + 1) * 136 + r], h1, l1);
        bsplit(Sw[(c8    ) * 136 + r], h2, l2);
        bsplit(Sw[(c8 + 1) * 136 + r], h3, l3);
        outp[ob + s * 128 + r] =
            make_uint4(bpack(h0, h1), bpack(h2, h3), bpack(l0, l1), bpack(l2, l3));
    }
}

__global__ __launch_bounds__(256) void pack_x(const float* __restrict__ A,
                                              uint4* __restrict__ outp) {
    __shared__ float Sx[128 * 36];
    const int t = threadIdx.x;
    const int m0 = blockIdx.x * 128, k0 = blockIdx.y * 32;
    #pragma unroll
    for (int i = 0; i < 4; i++) {
        const int idx = t + i * 256;
        const int row = idx >> 3, c4 = (idx & 7) * 4;
        *(float4*)&Sx[row * 36 + c4] =
            *(const float4*)(A + (size_t)(m0 + row) * KDIM + k0 + c4);
    }
    __syncthreads();
    const size_t ob = ((size_t)blockIdx.x * NCH + blockIdx.y) * 8 * 128;
    #pragma unroll
    for (int i = 0; i < 4; i++) {
        const int idx = t + i * 256;
        const int s = idx >> 7, r = idx & 127;
        const int c0 = (s >> 2) * 16 + 2 * (s & 3), c8 = c0 + 8;
        float h0, l0, h1, l1, h2, l2, h3, l3;
        bsplit(Sx[r * 36 + c0    ], h0, l0);
        bsplit(Sx[r * 36 + c0 + 1], h1, l1);
        bsplit(Sx[r * 36 + c8    ], h2, l2);
        bsplit(Sx[r * 36 + c8 + 1], h3, l3);
        outp[ob + s * 128 + r] =
            make_uint4(bpack(h0, h1), bpack(h2, h3), bpack(l0, l1), bpack(l2, l3));
    }
}

// ---------------------------------------------------------------------------
// 3xBF16 GEMM (R10 256-thread core). mode 0: qkv — epilogue packs q/k
// directly into flash fragment format (g_qpb/g_kqb), computes g_ksq, and
// writes v floats for vpack. mode 1: plain out + bias.
// Warp n-tiles are 64-wide and 64-aligned; head segments (192h+{0,64,128},
// each 64 long) never split a warp tile, so 'part' is warp-uniform.
// ---------------------------------------------------------------------------
#define BRS    130
#define BSTAGE (8*BRS)
#define GSMEM2 (2*2*BSTAGE*16)

__global__ __launch_bounds__(256) void bf16_gemm(
    const uint4* __restrict__ Ap,
    const uint4* __restrict__ Bp,
    const float* __restrict__ bias,
    float* __restrict__ outp, int mode)
{
    extern __shared__ uint4 sm4[];
    const uint32_t sbase = smem_u32(sm4);
    const int t = threadIdx.x, wid = t >> 5, lane = t & 31;
    const int qr = lane >> 2, qc = lane & 3;
    const int m0 = blockIdx.y * 128, n0 = blockIdx.x * 128;
    const int wm = (wid & 3) * 32, wn = (wid >> 2) * 64;

    float acc[2][8][4];
    #pragma unroll
    for (int i = 0; i < 2; i++)
        #pragma unroll
        for (int j = 0; j < 8; j++)
            #pragma unroll
            for (int e = 0; e < 4; e++) acc[i][j][e] = 0.f;

    auto LDST = [&](int c, int st) {
        const uint4* ag = Ap + ((size_t)blockIdx.y * NCH + c) * 8 * 128;
        const uint4* bg = Bp + ((size_t)blockIdx.x * NCH + c) * 8 * 128;
        const uint32_t ab = sbase + (uint32_t)(st * 2 * BSTAGE) * 16;
        const uint32_t bb = ab + (uint32_t)BSTAGE * 16;
        #pragma unroll
        for (int i = 0; i < 4; i++) {
            const int idx = t + i * 256;
            const int slot = idx >> 7, row = idx & 127;
            CP16(ab + (uint32_t)(slot * BRS + row) * 16, ag + idx);
            CP16(bb + (uint32_t)(slot * BRS + row) * 16, bg + idx);
        }
    };
    auto COMPUTE = [&](const uint4* __restrict__ As4, const uint4* __restrict__ Bs4) {
        #pragma unroll
        for (int ks = 0; ks < 2; ks++) {
            uint4 A0[2], A8[2];
            #pragma unroll
            for (int tm = 0; tm < 2; tm++) {
                const int mr = wm + tm * 16 + qr;
                A0[tm] = As4[(ks * 4 + qc) * BRS + mr];
                A8[tm] = As4[(ks * 4 + qc) * BRS + mr + 8];
            }
            #pragma unroll
            for (int tn = 0; tn < 8; tn++) {
                const uint4 Bf = Bs4[(ks * 4 + qc) * BRS + wn + tn * 8 + qr];
                #pragma unroll
                for (int tm = 0; tm < 2; tm++) {
                    float* d = acc[tm][tn];
                    mma_bf16(d, A0[tm].x, A8[tm].x, A0[tm].y, A8[tm].y, Bf.x, Bf.y);
                    mma_bf16(d, A0[tm].x, A8[tm].x, A0[tm].y, A8[tm].y, Bf.z, Bf.w);
                    mma_bf16(d, A0[tm].z, A8[tm].z, A0[tm].w, A8[tm].w, Bf.x, Bf.y);
                }
            }
        }
    };

    LDST(0, 0);
    CP_COMMIT();

    #pragma unroll 1
    for (int c = 0; c < NCH; c += 2) {
        if (c + 1 < NCH) { LDST(c + 1, 1); CP_COMMIT(); CP_WAIT1(); }
        else             { CP_WAIT0(); }
        __syncthreads();
        COMPUTE(sm4, sm4 + BSTAGE);
        __syncthreads();
        if (c + 2 < NCH) { LDST(c + 2, 0); CP_COMMIT(); CP_WAIT1(); }
        else             { CP_WAIT0(); }
        __syncthreads();
        COMPUTE(sm4 + 2 * BSTAGE, sm4 + 3 * BSTAGE);
        __syncthreads();
    }

    if (mode == 1) {
        #pragma unroll
        for (int tm = 0; tm < 2; tm++) {
            const int r0 = m0 + wm + tm * 16 + qr;
            #pragma unroll
            for (int tn = 0; tn < 8; tn++) {
                const int col = n0 + wn + tn * 8 + qc * 2;
                const float bz0 = bias[col], bz1 = bias[col + 1];
                #pragma unroll
                for (int half = 0; half < 2; half++) {
                    const int row = r0 + half * 8;
                    *(float2*)&outp[(size_t)row * DIM + col] =
                        make_float2(acc[tm][tn][half * 2 + 0] + bz0,
                                    acc[tm][tn][half * 2 + 1] + bz1);
                }
            }
        }
        return;
    }

    // mode 0: qkv epilogue with fused flash packing
    const int gc0  = n0 + wn;              // 64-aligned warp segment start
    const int h    = gc0 / 192;
    const int part = (gc0 - h * 192) >> 6; // 0=q, 1=k, 2=v (warp-uniform)

    #pragma unroll
    for (int tm = 0; tm < 2; tm++) {
        const int r0 = m0 + wm + tm * 16 + qr;
        #pragma unroll
        for (int half = 0; half < 2; half++) {
            const int row = r0 + half * 8;
            const int bb = row >> 11, s = row & (SEQ - 1);
            const size_t rowbase = (size_t)(bb * NH + h) * SEQ + s;
            const int e0 = half * 2;
            if (part == 2) {
                #pragma unroll
                for (int tn = 0; tn < 8; tn++) {
                    const int col = gc0 + tn * 8 + qc * 2;
                    const int dd = tn * 8 + qc * 2;
                    *(float2*)&g_v[rowbase * HD + dd] =
                        make_float2(acc[tm][tn][e0] + bias[col],
                                    acc[tm][tn][e0 + 1] + bias[col + 1]);
                }
            } else {
                float sksq = 0.f;
                #pragma unroll
                for (int tn = 0; tn < 8; tn += 2) {
                    const int col = gc0 + tn * 8 + qc * 2;
                    float v0 = acc[tm][tn    ][e0]     + bias[col];
                    float v1 = acc[tm][tn    ][e0 + 1] + bias[col + 1];
                    float v2 = acc[tm][tn + 1][e0]     + bias[col + 8];
                    float v3 = acc[tm][tn + 1][e0 + 1] + bias[col + 9];
                    if (part == 0) {
                        v0 *= C2LE; v1 *= C2LE; v2 *= C2LE; v3 *= C2LE;
                    } else {
                        sksq += v0 * v0 + v1 * v1 + v2 * v2 + v3 * v3;
                    }
                    float h0, l0, h1, l1, h2, l2, h3, l3;
                    bsplit(v0, h0, l0); bsplit(v1, h1, l1);
                    bsplit(v2, h2, l2); bsplit(v3, h3, l3);
                    const uint4 pk = make_uint4(bpack(h0, h1), bpack(h2, h3),
                                                bpack(l0, l1), bpack(l2, l3));
                    const int slot = (tn >> 1) * 4 + qc;
                    if (part == 0) g_qpb[rowbase * 16 + slot] = pk;
                    else           g_kqb[rowbase * 16 + slot] = pk;
                }
                if (part == 1) {
                    sksq += __shfl_xor_sync(0xffffffffu, sksq, 1);
                    sksq += __shfl_xor_sync(0xffffffffu, sksq, 2);
                    if (qc == 0) g_ksq[rowbase] = LOG2E * sksq;
                }
            }
        }
    }
}

// ---------------------------------------------------------------------------
// vpack: g_v floats -> g_vph fp16 key-paired (V-only remainder of old prep)
// ---------------------------------------------------------------------------
#define PSTAGE 68
#define VPACK_SMEM (64*PSTAGE*(int)sizeof(float))

__global__ __launch_bounds__(256) void vpack() {
    extern __shared__ float Sv[];
    const int t = threadIdx.x;
    const int bh = blockIdx.y, s0 = blockIdx.x * 64;
    const size_t base = (size_t)bh * SEQ * HD;

    #pragma unroll
    for (int i = 0; i < 4; i++) {
        const int li = t + i * 256;
        const int row = li >> 4, c4 = (li & 15) << 2;
        *(float4*)&Sv[row * PSTAGE + c4] =
            *(const float4*)(g_v + base + (size_t)(s0 + row) * HD + c4);
    }
    __syncthreads();

    const size_t vb = ((size_t)bh * (SEQ / 64) + (s0 >> 6)) * 2048;
    #pragma unroll
    for (int i = 0; i < 8; i++) {
        const int idx = t + i * 256;
        const int row = idx >> 7;
        const int rem = idx & 127;
        const int d = rem >> 1, which = rem & 1;
        const int ks = row >> 2, qcq = row & 3;
        const int p = ks * 8 + qcq + 4 * which;
        g_vph[vb + idx] = hpack(Sv[(2 * p) * PSTAGE + d], Sv[(2 * p + 1) * PSTAGE + d]);
    }
}

// ---------------------------------------------------------------------------
// Flash attention v7 (unchanged — known-good)
// ---------------------------------------------------------------------------
#define KB4S 20
#define KB_W (64*KB4S*4)
#define VST  136
#define VH_W (16*VST)
#define FLASH_SMEM ((KB_W + VH_W + 64)*(int)sizeof(float))

__global__ __launch_bounds__(128, 3) void flash_mma() {
    extern __shared__ float s[];
    uint4*    Kb4  = (uint4*)s;
    uint32_t* Vh   = (uint32_t*)s + KB_W;
    float*    ksqs = s + KB_W + VH_W;

    const int t = threadIdx.x, lane = t & 31, w = t >> 5;
    const int qr = lane >> 2, qc = lane & 3;
    const int wm = w * 16;
    const int bh = blockIdx.y;
    const int s0 = blockIdx.x * 64;
    const size_t rbase = (size_t)bh * SEQ;

    uint32_t qh[4][4], ql[4][4];
    {
        const uint4* q0 = g_qpb + (rbase + s0 + wm + qr) * 16;
        const uint4* q1 = q0 + 8 * 16;
        #pragma unroll
        for (int ks = 0; ks < 4; ks++) {
            const uint4 f0 = q0[ks * 4 + qc];
            const uint4 f1 = q1[ks * 4 + qc];
            qh[ks][0] = f0.x; qh[ks][1] = f1.x; qh[ks][2] = f0.y; qh[ks][3] = f1.y;
            ql[ks][0] = f0.z; ql[ks][1] = f1.z; ql[ks][2] = f0.w; ql[ks][3] = f1.w;
        }
    }

    float oacc[8][4];
    #pragma unroll
    for (int tn = 0; tn < 8; tn++)
        #pragma unroll
        for (int e = 0; e < 4; e++) oacc[tn][e] = 0.f;
    float m0r = -1e30f, m1r = -1e30f, l0r = 0.f, l1r = 0.f;

    for (int t0 = 0; t0 < SEQ; t0 += 64) {
        __syncthreads();
        {
            const uint4* kg = g_kqb + (rbase + t0) * 16;
            #pragma unroll
            for (int i = 0; i < 8; i++) {
                const int li = t + i * 128;
                const int row = li >> 4, slot = li & 15;
                Kb4[row * KB4S + slot] = kg[row * 16 + slot];
            }
        }
        {
            const uint4* vg = (const uint4*)g_vph +
                              ((size_t)bh * (SEQ / 64) + (t0 >> 6)) * 512;
            #pragma unroll
            for (int i = 0; i < 4; i++) {
                const int li = t + i * 128;
                const int row = li >> 5, rem = (li & 31) * 4;
                *(uint4*)&Vh[row * VST + rem] = vg[li];
            }
        }
        if (t < 64) ksqs[t] = g_ksq[rbase + t0 + t];
        __syncthreads();

        float sacc[8][4];
        #pragma unroll
        for (int tn = 0; tn < 8; tn++)
            #pragma unroll
            for (int e = 0; e < 4; e++) sacc[tn][e] = 0.f;

        #pragma unroll
        for (int ks = 0; ks < 4; ks++) {
            #pragma unroll
            for (int tn = 0; tn < 8; tn++) {
                const uint4 wv = Kb4[(tn * 8 + qr) * KB4S + ks * 4 + qc];
                float* d = sacc[tn];
                mma_bf16(d, qh[ks][0], qh[ks][1], qh[ks][2], qh[ks][3], wv.x, wv.y);
                mma_bf16(d, qh[ks][0], qh[ks][1], qh[ks][2], qh[ks][3], wv.z, wv.w);
                mma_bf16(d, ql[ks][0], ql[ks][1], ql[ks][2], ql[ks][3], wv.x, wv.y);
            }
        }

        float mx0 = -1e30f, mx1 = -1e30f;
        const float2* ksq2 = (const float2*)ksqs;
        #pragma unroll
        for (int tn = 0; tn < 8; tn++) {
            const float2 kk = ksq2[tn * 4 + qc];
            sacc[tn][0] -= kk.x; sacc[tn][1] -= kk.y;
            sacc[tn][2] -= kk.x; sacc[tn][3] -= kk.y;
            mx0 = fmaxf(mx0, fmaxf(sacc[tn][0], sacc[tn][1]));
            mx1 = fmaxf(mx1, fmaxf(sacc[tn][2], sacc[tn][3]));
        }
        #pragma unroll
        for (int off = 1; off <= 2; off <<= 1) {
            mx0 = fmaxf(mx0, __shfl_xor_sync(0xffffffffu, mx0, off));
            mx1 = fmaxf(mx1, __shfl_xor_sync(0xffffffffu, mx1, off));
        }
        const float mn0 = fmaxf(m0r, mx0), mn1 = fmaxf(m1r, mx1);
        const float al0 = ex2f(m0r - mn0), al1 = ex2f(m1r - mn1);
        m0r = mn0; m1r = mn1;

        float rs0 = 0.f, rs1 = 0.f;
        #pragma unroll
        for (int tn = 0; tn < 8; tn++) {
            sacc[tn][0] = ex2f(sacc[tn][0] - mn0);
            sacc[tn][1] = ex2f(sacc[tn][1] - mn0);
            sacc[tn][2] = ex2f(sacc[tn][2] - mn1);
            sacc[tn][3] = ex2f(sacc[tn][3] - mn1);
            rs0 += sacc[tn][0] + sacc[tn][1];
            rs1 += sacc[tn][2] + sacc[tn][3];
            oacc[tn][0] *= al0; oacc[tn][1] *= al0;
            oacc[tn][2] *= al1; oacc[tn][3] *= al1;
        }
        l0r = l0r * al0 + rs0;
        l1r = l1r * al1 + rs1;

        #pragma unroll
        for (int ks = 0; ks < 4; ks++) {
            const uint32_t a0 = hpack(sacc[2*ks    ][0], sacc[2*ks    ][1]);
            const uint32_t a1 = hpack(sacc[2*ks    ][2], sacc[2*ks    ][3]);
            const uint32_t a2 = hpack(sacc[2*ks + 1][0], sacc[2*ks + 1][1]);
            const uint32_t a3 = hpack(sacc[2*ks + 1][2], sacc[2*ks + 1][3]);
            #pragma unroll
            for (int tn = 0; tn < 8; tn++) {
                const uint2 b01 =
                    *(const uint2*)&Vh[(ks * 4 + qc) * VST + (tn * 8 + qr) * 2];
                mma_f16(oacc[tn], a0, a1, a2, a3, b01.x, b01.y);
            }
        }
    }

    #pragma unroll
    for (int off = 1; off <= 2; off <<= 1) {
        l0r += __shfl_xor_sync(0xffffffffu, l0r, off);
        l1r += __shfl_xor_sync(0xffffffffu, l1r, off);
    }
    const float inv0 = 1.f / l0r, inv1 = 1.f / l1r;
    const int b = bh >> 4, h = bh & 15;

    #pragma unroll
    for (int half = 0; half < 2; half++) {
        const int m = b * SEQ + s0 + wm + qr + half * 8;
        const int mblk = m >> 7, r = m & 127;
        const float inv = half ? inv1 : inv0;
        const int e0 = half * 2;
        #pragma unroll
        for (int tn = 0; tn < 8; tn += 2) {
            const int g = tn * 8 + 2 * qc;
            const int cglob = 2 * h + (g >> 5);
            const int sslot = ((g >> 4) & 1) * 4 + qc;
            float h0, l0, h1, l1, h2, l2, h3, l3;
            bsplit(oacc[tn    ][e0    ] * inv, h0, l0);
            bsplit(oacc[tn    ][e0 + 1] * inv, h1, l1);
            bsplit(oacc[tn + 1][e0    ] * inv, h2, l2);
            bsplit(oacc[tn + 1][e0 + 1] * inv, h3, l3);
            g_attp[((size_t)mblk * NCH + cglob) * 8 * 128 + sslot * 128 + r] =
                make_uint4(bpack(h0, h1), bpack(h2, h3), bpack(l0, l1), bpack(l2, l3));
        }
    }
}

// ---------------------------------------------------------------------------
extern "C" void kernel_launch(void* const* d_in, const int* in_sizes, int n_in,
                              void* d_out, int out_size) {
    (void)in_sizes; (void)n_in; (void)out_size;
    const float* x    = (const float*)d_in[0];
    const float* Wqkv = (const float*)d_in[1];
    const float* bqkv = (const float*)d_in[2];
    const float* Wo   = (const float*)d_in[3];
    const float* bo   = (const float*)d_in[4];
    float*       out  = (float*)d_out;

    uint4* xp;   cudaGetSymbolAddress((void**)&xp,   g_xp);
    uint4* attp; cudaGetSymbolAddress((void**)&attp, g_attp);
    uint4* wqp;  cudaGetSymbolAddress((void**)&wqp,  g_wqp);
    uint4* wop;  cudaGetSymbolAddress((void**)&wop,  g_wop);

    cudaFuncSetAttribute(bf16_gemm, cudaFuncAttributeMaxDynamicSharedMemorySize, GSMEM2);
    cudaFuncSetAttribute(vpack, cudaFuncAttributeMaxDynamicSharedMemorySize, VPACK_SMEM);
    cudaFuncSetAttribute(flash_mma, cudaFuncAttributeMaxDynamicSharedMemorySize, FLASH_SMEM);

    pack_w<<<dim3(N_QKV/128, NCH), 256>>>(Wqkv, wqp, N_QKV);
    pack_w<<<dim3(DIM/128,  NCH), 256>>>(Wo,   wop, DIM);
    pack_x<<<dim3(M_ROWS/128, NCH), 256>>>(x, xp);

    bf16_gemm<<<dim3(N_QKV/128, M_ROWS/128), 256, GSMEM2>>>(xp, wqp, bqkv, nullptr, 0);

    vpack<<<dim3(SEQ/64, NUM_B*NH), 256, VPACK_SMEM>>>();

    flash_mma<<<dim3(SEQ/64, NUM_B*NH), 128, FLASH_SMEM>>>();

    bf16_gemm<<<dim3(DIM/128, M_ROWS/128), 256, GSMEM2>>>(attp, wop, bo, out, 1);
}

// round 13
// speedup vs baseline: 1.0750x; 1.0750x over previous
#include <cuda_runtime.h>
#include <cuda_bf16.h>
#include <cuda_fp16.h>
#include <cstdint>

#define NUM_B 2
#define SEQ   2048
#define DIM   1024
#define NH    16
#define HD    64
#define M_ROWS (NUM_B*SEQ)
#define N_QKV  (3*DIM)
#define KDIM   DIM
#define NCH    (KDIM/32)

#define LOG2E 1.4426950408889634f
#define C2LE  2.8853900817779268f

// Scratch
__device__ float g_v  [(size_t)NUM_B*NH*SEQ*HD];
// bf16 hi/lo fragment-packed GEMM operands
__device__ uint4 g_xp  [(size_t)M_ROWS*256];
__device__ uint4 g_attp[(size_t)M_ROWS*256];
__device__ uint4 g_wqp [(size_t)N_QKV*256];
__device__ uint4 g_wop [(size_t)DIM*256];
// flash operands (q/k packed directly by qkv epilogue)
__device__ uint4    g_qpb[(size_t)NUM_B*NH*SEQ*16];
__device__ uint4    g_kqb[(size_t)NUM_B*NH*SEQ*16];
__device__ uint32_t g_vph[(size_t)NUM_B*NH*SEQ*32];
__device__ float    g_ksq[(size_t)NUM_B*NH*SEQ];

// ---------------------------------------------------------------------------
// Helpers
// ---------------------------------------------------------------------------
__device__ __forceinline__ float ex2f(float x) {
    float r;
    asm("ex2.approx.f32 %0, %1;" : "=f"(r) : "f"(x));
    return r;
}
__device__ __forceinline__ void bsplit(float x, float& h, float& l) {
    h = __bfloat162float(__float2bfloat16_rn(x));
    l = x - h;
}
__device__ __forceinline__ uint32_t bpack(float a, float b) {
    __nv_bfloat162 t = __floats2bfloat162_rn(a, b);
    return *(uint32_t*)&t;
}
__device__ __forceinline__ uint32_t hpack(float a, float b) {
    __half2 t = __floats2half2_rn(a, b);
    return *(uint32_t*)&t;
}
__device__ __forceinline__ void mma_bf16(float* d,
                                         uint32_t a0, uint32_t a1, uint32_t a2, uint32_t a3,
                                         uint32_t b0, uint32_t b1) {
    asm volatile(
        "mma.sync.aligned.m16n8k16.row.col.f32.bf16.bf16.f32 "
        "{%0,%1,%2,%3}, {%4,%5,%6,%7}, {%8,%9}, {%0,%1,%2,%3};"
        : "+f"(d[0]), "+f"(d[1]), "+f"(d[2]), "+f"(d[3])
        : "r"(a0), "r"(a1), "r"(a2), "r"(a3), "r"(b0), "r"(b1));
}
__device__ __forceinline__ void mma_f16(float* d,
                                        uint32_t a0, uint32_t a1, uint32_t a2, uint32_t a3,
                                        uint32_t b0, uint32_t b1) {
    asm volatile(
        "mma.sync.aligned.m16n8k16.row.col.f32.f16.f16.f32 "
        "{%0,%1,%2,%3}, {%4,%5,%6,%7}, {%8,%9}, {%0,%1,%2,%3};"
        : "+f"(d[0]), "+f"(d[1]), "+f"(d[2]), "+f"(d[3])
        : "r"(a0), "r"(a1), "r"(a2), "r"(a3), "r"(b0), "r"(b1));
}
#define U(x) __float_as_uint(x)
#define CP16(dst, src) \
    asm volatile("cp.async.cg.shared.global [%0], [%1], 16;" :: "r"(dst), "l"(src))
#define CP_COMMIT() asm volatile("cp.async.commit_group;" ::: "memory")
#define CP_WAIT1()  asm volatile("cp.async.wait_group 1;" ::: "memory")
#define CP_WAIT0()  asm volatile("cp.async.wait_group 0;" ::: "memory")
__device__ __forceinline__ uint32_t smem_u32(const void* p) {
    uint32_t a;
    asm("{ .reg .u64 t; cvta.to.shared.u64 t, %1; cvt.u32.u64 %0, t; }"
        : "=r"(a) : "l"(p));
    return a;
}

// ---------------------------------------------------------------------------
// pack_w / pack_x (unchanged)
// ---------------------------------------------------------------------------
__global__ __launch_bounds__(256) void pack_w(const float* __restrict__ W,
                                              uint4* __restrict__ outp, int N) {
    __shared__ float Sw[32 * 136];
    const int t = threadIdx.x;
    const int n0 = blockIdx.x * 128, k0 = blockIdx.y * 32;
    #pragma unroll
    for (int i = 0; i < 4; i++) {
        const int idx = t + i * 256;
        const int kr = idx >> 5, c4 = (idx & 31) * 4;
        *(float4*)&Sw[kr * 136 + c4] =
            *(const float4*)(W + (size_t)(k0 + kr) * N + n0 + c4);
    }
    __syncthreads();
    const size_t ob = ((size_t)blockIdx.x * NCH + blockIdx.y) * 8 * 128;
    #pragma unroll
    for (int i = 0; i < 4; i++) {
        const int idx = t + i * 256;
        const int s = idx >> 7, r = idx & 127;
        const int c0 = (s >> 2) * 16 + 2 * (s & 3), c8 = c0 + 8;
        float h0, l0, h1, l1, h2, l2, h3, l3;
        bsplit(Sw[(c0    ) * 136 + r], h0, l0);
        bsplit(Sw[(c0 + 1) * 136 + r], h1, l1);
        bsplit(Sw[(c8    ) * 136 + r], h2, l2);
        bsplit(Sw[(c8 + 1) * 136 + r], h3, l3);
        outp[ob + s * 128 + r] =
            make_uint4(bpack(h0, h1), bpack(h2, h3), bpack(l0, l1), bpack(l2, l3));
    }
}

__global__ __launch_bounds__(256) void pack_x(const float* __restrict__ A,
                                              uint4* __restrict__ outp) {
    __shared__ float Sx[128 * 36];
    const int t = threadIdx.x;
    const int m0 = blockIdx.x * 128, k0 = blockIdx.y * 32;
    #pragma unroll
    for (int i = 0; i < 4; i++) {
        const int idx = t + i * 256;
        const int row = idx >> 3, c4 = (idx & 7) * 4;
        *(float4*)&Sx[row * 36 + c4] =
            *(const float4*)(A + (size_t)(m0 + row) * KDIM + k0 + c4);
    }
    __syncthreads();
    const size_t ob = ((size_t)blockIdx.x * NCH + blockIdx.y) * 8 * 128;
    #pragma unroll
    for (int i = 0; i < 4; i++) {
        const int idx = t + i * 256;
        const int s = idx >> 7, r = idx & 127;
        const int c0 = (s >> 2) * 16 + 2 * (s & 3), c8 = c0 + 8;
        float h0, l0, h1, l1, h2, l2, h3, l3;
        bsplit(Sx[r * 36 + c0    ], h0, l0);
        bsplit(Sx[r * 36 + c0 + 1], h1, l1);
        bsplit(Sx[r * 36 + c8    ], h2, l2);
        bsplit(Sx[r * 36 + c8 + 1], h3, l3);
        outp[ob + s * 128 + r] =
            make_uint4(bpack(h0, h1), bpack(h2, h3), bpack(l0, l1), bpack(l2, l3));
    }
}

// ---------------------------------------------------------------------------
// 3xBF16 GEMM with fused qkv pack epilogue. __launch_bounds__(256, 2)
// caps regs at 128 so 2 CTAs/SM fit (R12's regs=138 -> 1 CTA was the
// regression mechanism); extra epilogue pressure spills locally, post-loop.
// ---------------------------------------------------------------------------
#define BRS    130
#define BSTAGE (8*BRS)
#define GSMEM2 (2*2*BSTAGE*16)

__global__ __launch_bounds__(256, 2) void bf16_gemm(
    const uint4* __restrict__ Ap,
    const uint4* __restrict__ Bp,
    const float* __restrict__ bias,
    float* __restrict__ outp, int mode)
{
    extern __shared__ uint4 sm4[];
    const uint32_t sbase = smem_u32(sm4);
    const int t = threadIdx.x, wid = t >> 5, lane = t & 31;
    const int qr = lane >> 2, qc = lane & 3;
    const int m0 = blockIdx.y * 128, n0 = blockIdx.x * 128;
    const int wm = (wid & 3) * 32, wn = (wid >> 2) * 64;

    float acc[2][8][4];
    #pragma unroll
    for (int i = 0; i < 2; i++)
        #pragma unroll
        for (int j = 0; j < 8; j++)
            #pragma unroll
            for (int e = 0; e < 4; e++) acc[i][j][e] = 0.f;

    auto LDST = [&](int c, int st) {
        const uint4* ag = Ap + ((size_t)blockIdx.y * NCH + c) * 8 * 128;
        const uint4* bg = Bp + ((size_t)blockIdx.x * NCH + c) * 8 * 128;
        const uint32_t ab = sbase + (uint32_t)(st * 2 * BSTAGE) * 16;
        const uint32_t bb = ab + (uint32_t)BSTAGE * 16;
        #pragma unroll
        for (int i = 0; i < 4; i++) {
            const int idx = t + i * 256;
            const int slot = idx >> 7, row = idx & 127;
            CP16(ab + (uint32_t)(slot * BRS + row) * 16, ag + idx);
            CP16(bb + (uint32_t)(slot * BRS + row) * 16, bg + idx);
        }
    };
    auto COMPUTE = [&](const uint4* __restrict__ As4, const uint4* __restrict__ Bs4) {
        #pragma unroll
        for (int ks = 0; ks < 2; ks++) {
            uint4 A0[2], A8[2];
            #pragma unroll
            for (int tm = 0; tm < 2; tm++) {
                const int mr = wm + tm * 16 + qr;
                A0[tm] = As4[(ks * 4 + qc) * BRS + mr];
                A8[tm] = As4[(ks * 4 + qc) * BRS + mr + 8];
            }
            #pragma unroll
            for (int tn = 0; tn < 8; tn++) {
                const uint4 Bf = Bs4[(ks * 4 + qc) * BRS + wn + tn * 8 + qr];
                #pragma unroll
                for (int tm = 0; tm < 2; tm++) {
                    float* d = acc[tm][tn];
                    mma_bf16(d, A0[tm].x, A8[tm].x, A0[tm].y, A8[tm].y, Bf.x, Bf.y);
                    mma_bf16(d, A0[tm].x, A8[tm].x, A0[tm].y, A8[tm].y, Bf.z, Bf.w);
                    mma_bf16(d, A0[tm].z, A8[tm].z, A0[tm].w, A8[tm].w, Bf.x, Bf.y);
                }
            }
        }
    };

    LDST(0, 0);
    CP_COMMIT();

    #pragma unroll 1
    for (int c = 0; c < NCH; c += 2) {
        if (c + 1 < NCH) { LDST(c + 1, 1); CP_COMMIT(); CP_WAIT1(); }
        else             { CP_WAIT0(); }
        __syncthreads();
        COMPUTE(sm4, sm4 + BSTAGE);
        __syncthreads();
        if (c + 2 < NCH) { LDST(c + 2, 0); CP_COMMIT(); CP_WAIT1(); }
        else             { CP_WAIT0(); }
        __syncthreads();
        COMPUTE(sm4 + 2 * BSTAGE, sm4 + 3 * BSTAGE);
        __syncthreads();
    }

    if (mode == 1) {
        #pragma unroll
        for (int tm = 0; tm < 2; tm++) {
            const int r0 = m0 + wm + tm * 16 + qr;
            #pragma unroll
            for (int tn = 0; tn < 8; tn++) {
                const int col = n0 + wn + tn * 8 + qc * 2;
                const float bz0 = bias[col], bz1 = bias[col + 1];
                #pragma unroll
                for (int half = 0; half < 2; half++) {
                    const int row = r0 + half * 8;
                    *(float2*)&outp[(size_t)row * DIM + col] =
                        make_float2(acc[tm][tn][half * 2 + 0] + bz0,
                                    acc[tm][tn][half * 2 + 1] + bz1);
                }
            }
        }
        return;
    }

    // mode 0: qkv epilogue with fused flash packing
    const int gc0  = n0 + wn;
    const int h    = gc0 / 192;
    const int part = (gc0 - h * 192) >> 6;

    #pragma unroll
    for (int tm = 0; tm < 2; tm++) {
        const int r0 = m0 + wm + tm * 16 + qr;
        #pragma unroll
        for (int half = 0; half < 2; half++) {
            const int row = r0 + half * 8;
            const int bb = row >> 11, s = row & (SEQ - 1);
            const size_t rowbase = (size_t)(bb * NH + h) * SEQ + s;
            const int e0 = half * 2;
            if (part == 2) {
                #pragma unroll
                for (int tn = 0; tn < 8; tn++) {
                    const int col = gc0 + tn * 8 + qc * 2;
                    const int dd = tn * 8 + qc * 2;
                    *(float2*)&g_v[rowbase * HD + dd] =
                        make_float2(acc[tm][tn][e0] + bias[col],
                                    acc[tm][tn][e0 + 1] + bias[col + 1]);
                }
            } else {
                float sksq = 0.f;
                #pragma unroll
                for (int tn = 0; tn < 8; tn += 2) {
                    const int col = gc0 + tn * 8 + qc * 2;
                    float v0 = acc[tm][tn    ][e0]     + bias[col];
                    float v1 = acc[tm][tn    ][e0 + 1] + bias[col + 1];
                    float v2 = acc[tm][tn + 1][e0]     + bias[col + 8];
                    float v3 = acc[tm][tn + 1][e0 + 1] + bias[col + 9];
                    if (part == 0) {
                        v0 *= C2LE; v1 *= C2LE; v2 *= C2LE; v3 *= C2LE;
                    } else {
                        sksq += v0 * v0 + v1 * v1 + v2 * v2 + v3 * v3;
                    }
                    float h0, l0, h1, l1, h2, l2, h3, l3;
                    bsplit(v0, h0, l0); bsplit(v1, h1, l1);
                    bsplit(v2, h2, l2); bsplit(v3, h3, l3);
                    const uint4 pk = make_uint4(bpack(h0, h1), bpack(h2, h3),
                                                bpack(l0, l1), bpack(l2, l3));
                    const int slot = (tn >> 1) * 4 + qc;
                    if (part == 0) g_qpb[rowbase * 16 + slot] = pk;
                    else           g_kqb[rowbase * 16 + slot] = pk;
                }
                if (part == 1) {
                    sksq += __shfl_xor_sync(0xffffffffu, sksq, 1);
                    sksq += __shfl_xor_sync(0xffffffffu, sksq, 2);
                    if (qc == 0) g_ksq[rowbase] = LOG2E * sksq;
                }
            }
        }
    }
}

// ---------------------------------------------------------------------------
// vpack: g_v floats -> g_vph fp16 key-paired
// ---------------------------------------------------------------------------
#define PSTAGE 68
#define VPACK_SMEM (64*PSTAGE*(int)sizeof(float))

__global__ __launch_bounds__(256) void vpack() {
    extern __shared__ float Sv[];
    const int t = threadIdx.x;
    const int bh = blockIdx.y, s0 = blockIdx.x * 64;
    const size_t base = (size_t)bh * SEQ * HD;

    #pragma unroll
    for (int i = 0; i < 4; i++) {
        const int li = t + i * 256;
        const int row = li >> 4, c4 = (li & 15) << 2;
        *(float4*)&Sv[row * PSTAGE + c4] =
            *(const float4*)(g_v + base + (size_t)(s0 + row) * HD + c4);
    }
    __syncthreads();

    const size_t vb = ((size_t)bh * (SEQ / 64) + (s0 >> 6)) * 2048;
    #pragma unroll
    for (int i = 0; i < 8; i++) {
        const int idx = t + i * 256;
        const int row = idx >> 7;
        const int rem = idx & 127;
        const int d = rem >> 1, which = rem & 1;
        const int ks = row >> 2, qcq = row & 3;
        const int p = ks * 8 + qcq + 4 * which;
        g_vph[vb + idx] = hpack(Sv[(2 * p) * PSTAGE + d], Sv[(2 * p + 1) * PSTAGE + d]);
    }
}

// ---------------------------------------------------------------------------
// Flash attention v7 (unchanged — known-good)
// ---------------------------------------------------------------------------
#define KB4S 20
#define KB_W (64*KB4S*4)
#define VST  136
#define VH_W (16*VST)
#define FLASH_SMEM ((KB_W + VH_W + 64)*(int)sizeof(float))

__global__ __launch_bounds__(128, 3) void flash_mma() {
    extern __shared__ float s[];
    uint4*    Kb4  = (uint4*)s;
    uint32_t* Vh   = (uint32_t*)s + KB_W;
    float*    ksqs = s + KB_W + VH_W;

    const int t = threadIdx.x, lane = t & 31, w = t >> 5;
    const int qr = lane >> 2, qc = lane & 3;
    const int wm = w * 16;
    const int bh = blockIdx.y;
    const int s0 = blockIdx.x * 64;
    const size_t rbase = (size_t)bh * SEQ;

    uint32_t qh[4][4], ql[4][4];
    {
        const uint4* q0 = g_qpb + (rbase + s0 + wm + qr) * 16;
        const uint4* q1 = q0 + 8 * 16;
        #pragma unroll
        for (int ks = 0; ks < 4; ks++) {
            const uint4 f0 = q0[ks * 4 + qc];
            const uint4 f1 = q1[ks * 4 + qc];
            qh[ks][0] = f0.x; qh[ks][1] = f1.x; qh[ks][2] = f0.y; qh[ks][3] = f1.y;
            ql[ks][0] = f0.z; ql[ks][1] = f1.z; ql[ks][2] = f0.w; ql[ks][3] = f1.w;
        }
    }

    float oacc[8][4];
    #pragma unroll
    for (int tn = 0; tn < 8; tn++)
        #pragma unroll
        for (int e = 0; e < 4; e++) oacc[tn][e] = 0.f;
    float m0r = -1e30f, m1r = -1e30f, l0r = 0.f, l1r = 0.f;

    for (int t0 = 0; t0 < SEQ; t0 += 64) {
        __syncthreads();
        {
            const uint4* kg = g_kqb + (rbase + t0) * 16;
            #pragma unroll
            for (int i = 0; i < 8; i++) {
                const int li = t + i * 128;
                const int row = li >> 4, slot = li & 15;
                Kb4[row * KB4S + slot] = kg[row * 16 + slot];
            }
        }
        {
            const uint4* vg = (const uint4*)g_vph +
                              ((size_t)bh * (SEQ / 64) + (t0 >> 6)) * 512;
            #pragma unroll
            for (int i = 0; i < 4; i++) {
                const int li = t + i * 128;
                const int row = li >> 5, rem = (li & 31) * 4;
                *(uint4*)&Vh[row * VST + rem] = vg[li];
            }
        }
        if (t < 64) ksqs[t] = g_ksq[rbase + t0 + t];
        __syncthreads();

        float sacc[8][4];
        #pragma unroll
        for (int tn = 0; tn < 8; tn++)
            #pragma unroll
            for (int e = 0; e < 4; e++) sacc[tn][e] = 0.f;

        #pragma unroll
        for (int ks = 0; ks < 4; ks++) {
            #pragma unroll
            for (int tn = 0; tn < 8; tn++) {
                const uint4 wv = Kb4[(tn * 8 + qr) * KB4S + ks * 4 + qc];
                float* d = sacc[tn];
                mma_bf16(d, qh[ks][0], qh[ks][1], qh[ks][2], qh[ks][3], wv.x, wv.y);
                mma_bf16(d, qh[ks][0], qh[ks][1], qh[ks][2], qh[ks][3], wv.z, wv.w);
                mma_bf16(d, ql[ks][0], ql[ks][1], ql[ks][2], ql[ks][3], wv.x, wv.y);
            }
        }

        float mx0 = -1e30f, mx1 = -1e30f;
        const float2* ksq2 = (const float2*)ksqs;
        #pragma unroll
        for (int tn = 0; tn < 8; tn++) {
            const float2 kk = ksq2[tn * 4 + qc];
            sacc[tn][0] -= kk.x; sacc[tn][1] -= kk.y;
            sacc[tn][2] -= kk.x; sacc[tn][3] -= kk.y;
            mx0 = fmaxf(mx0, fmaxf(sacc[tn][0], sacc[tn][1]));
            mx1 = fmaxf(mx1, fmaxf(sacc[tn][2], sacc[tn][3]));
        }
        #pragma unroll
        for (int off = 1; off <= 2; off <<= 1) {
            mx0 = fmaxf(mx0, __shfl_xor_sync(0xffffffffu, mx0, off));
            mx1 = fmaxf(mx1, __shfl_xor_sync(0xffffffffu, mx1, off));
        }
        const float mn0 = fmaxf(m0r, mx0), mn1 = fmaxf(m1r, mx1);
        const float al0 = ex2f(m0r - mn0), al1 = ex2f(m1r - mn1);
        m0r = mn0; m1r = mn1;

        float rs0 = 0.f, rs1 = 0.f;
        #pragma unroll
        for (int tn = 0; tn < 8; tn++) {
            sacc[tn][0] = ex2f(sacc[tn][0] - mn0);
            sacc[tn][1] = ex2f(sacc[tn][1] - mn0);
            sacc[tn][2] = ex2f(sacc[tn][2] - mn1);
            sacc[tn][3] = ex2f(sacc[tn][3] - mn1);
            rs0 += sacc[tn][0] + sacc[tn][1];
            rs1 += sacc[tn][2] + sacc[tn][3];
            oacc[tn][0] *= al0; oacc[tn][1] *= al0;
            oacc[tn][2] *= al1; oacc[tn][3] *= al1;
        }
        l0r = l0r * al0 + rs0;
        l1r = l1r * al1 + rs1;

        #pragma unroll
        for (int ks = 0; ks < 4; ks++) {
            const uint32_t a0 = hpack(sacc[2*ks    ][0], sacc[2*ks    ][1]);
            const uint32_t a1 = hpack(sacc[2*ks    ][2], sacc[2*ks    ][3]);
            const uint32_t a2 = hpack(sacc[2*ks + 1][0], sacc[2*ks + 1][1]);
            const uint32_t a3 = hpack(sacc[2*ks + 1][2], sacc[2*ks + 1][3]);
            #pragma unroll
            for (int tn = 0; tn < 8; tn++) {
                const uint2 b01 =
                    *(const uint2*)&Vh[(ks * 4 + qc) * VST + (tn * 8 + qr) * 2];
                mma_f16(oacc[tn], a0, a1, a2, a3, b01.x, b01.y);
            }
        }
    }

    #pragma unroll
    for (int off = 1; off <= 2; off <<= 1) {
        l0r += __shfl_xor_sync(0xffffffffu, l0r, off);
        l1r += __shfl_xor_sync(0xffffffffu, l1r, off);
    }
    const float inv0 = 1.f / l0r, inv1 = 1.f / l1r;
    const int b = bh >> 4, h = bh & 15;

    #pragma unroll
    for (int half = 0; half < 2; half++) {
        const int m = b * SEQ + s0 + wm + qr + half * 8;
        const int mblk = m >> 7, r = m & 127;
        const float inv = half ? inv1 : inv0;
        const int e0 = half * 2;
        #pragma unroll
        for (int tn = 0; tn < 8; tn += 2) {
            const int g = tn * 8 + 2 * qc;
            const int cglob = 2 * h + (g >> 5);
            const int sslot = ((g >> 4) & 1) * 4 + qc;
            float h0, l0, h1, l1, h2, l2, h3, l3;
            bsplit(oacc[tn    ][e0    ] * inv, h0, l0);
            bsplit(oacc[tn    ][e0 + 1] * inv, h1, l1);
            bsplit(oacc[tn + 1][e0    ] * inv, h2, l2);
            bsplit(oacc[tn + 1][e0 + 1] * inv, h3, l3);
            g_attp[((size_t)mblk * NCH + cglob) * 8 * 128 + sslot * 128 + r] =
                make_uint4(bpack(h0, h1), bpack(h2, h3), bpack(l0, l1), bpack(l2, l3));
        }
    }
}

// ---------------------------------------------------------------------------
extern "C" void kernel_launch(void* const* d_in, const int* in_sizes, int n_in,
                              void* d_out, int out_size) {
    (void)in_sizes; (void)n_in; (void)out_size;
    const float* x    = (const float*)d_in[0];
    const float* Wqkv = (const float*)d_in[1];
    const float* bqkv = (const float*)d_in[2];
    const float* Wo   = (const float*)d_in[3];
    const float* bo   = (const float*)d_in[4];
    float*       out  = (float*)d_out;

    uint4* xp;   cudaGetSymbolAddress((void**)&xp,   g_xp);
    uint4* attp; cudaGetSymbolAddress((void**)&attp, g_attp);
    uint4* wqp;  cudaGetSymbolAddress((void**)&wqp,  g_wqp);
    uint4* wop;  cudaGetSymbolAddress((void**)&wop,  g_wop);

    cudaFuncSetAttribute(bf16_gemm, cudaFuncAttributeMaxDynamicSharedMemorySize, GSMEM2);
    cudaFuncSetAttribute(vpack, cudaFuncAttributeMaxDynamicSharedMemorySize, VPACK_SMEM);
    cudaFuncSetAttribute(flash_mma, cudaFuncAttributeMaxDynamicSharedMemorySize, FLASH_SMEM);

    pack_w<<<dim3(N_QKV/128, NCH), 256>>>(Wqkv, wqp, N_QKV);
    pack_w<<<dim3(DIM/128,  NCH), 256>>>(Wo,   wop, DIM);
    pack_x<<<dim3(M_ROWS/128, NCH), 256>>>(x, xp);

    bf16_gemm<<<dim3(N_QKV/128, M_ROWS/128), 256, GSMEM2>>>(xp, wqp, bqkv, nullptr, 0);

    vpack<<<dim3(SEQ/64, NUM_B*NH), 256, VPACK_SMEM>>>();

    flash_mma<<<dim3(SEQ/64, NUM_B*NH), 128, FLASH_SMEM>>>();

    bf16_gemm<<<dim3(DIM/128, M_ROWS/128), 256, GSMEM2>>>(attp, wop, bo, out, 1);
}

// round 14
// speedup vs baseline: 1.1174x; 1.0394x over previous
#include <cuda_runtime.h>
#include <cuda_bf16.h>
#include <cuda_fp16.h>
#include <cstdint>

#define NUM_B 2
#define SEQ   2048
#define DIM   1024
#define NH    16
#define HD    64
#define M_ROWS (NUM_B*SEQ)
#define N_QKV  (3*DIM)
#define KDIM   DIM
#define NCH    (KDIM/32)

#define LOG2E 1.4426950408889634f
#define C2LE  2.8853900817779268f

// Scratch
__device__ float g_v  [(size_t)NUM_B*NH*SEQ*HD];
// bf16 hi/lo fragment-packed GEMM operands
__device__ uint4 g_xp  [(size_t)M_ROWS*256];
__device__ uint4 g_attp[(size_t)M_ROWS*256];
__device__ uint4 g_wqp [(size_t)N_QKV*256];
__device__ uint4 g_wop [(size_t)DIM*256];
// flash operands (q/k packed directly by qkv epilogue)
__device__ uint4    g_qpb[(size_t)NUM_B*NH*SEQ*16];
__device__ uint4    g_kqb[(size_t)NUM_B*NH*SEQ*16];
__device__ uint32_t g_vph[(size_t)NUM_B*NH*SEQ*32];
__device__ float    g_ksq[(size_t)NUM_B*NH*SEQ];

// ---------------------------------------------------------------------------
// Helpers
// ---------------------------------------------------------------------------
__device__ __forceinline__ float ex2f(float x) {
    float r;
    asm("ex2.approx.f32 %0, %1;" : "=f"(r) : "f"(x));
    return r;
}
__device__ __forceinline__ void bsplit(float x, float& h, float& l) {
    h = __bfloat162float(__float2bfloat16_rn(x));
    l = x - h;
}
__device__ __forceinline__ uint32_t bpack(float a, float b) {
    __nv_bfloat162 t = __floats2bfloat162_rn(a, b);
    return *(uint32_t*)&t;
}
__device__ __forceinline__ uint32_t hpack(float a, float b) {
    __half2 t = __floats2half2_rn(a, b);
    return *(uint32_t*)&t;
}
__device__ __forceinline__ void mma_bf16(float* d,
                                         uint32_t a0, uint32_t a1, uint32_t a2, uint32_t a3,
                                         uint32_t b0, uint32_t b1) {
    asm volatile(
        "mma.sync.aligned.m16n8k16.row.col.f32.bf16.bf16.f32 "
        "{%0,%1,%2,%3}, {%4,%5,%6,%7}, {%8,%9}, {%0,%1,%2,%3};"
        : "+f"(d[0]), "+f"(d[1]), "+f"(d[2]), "+f"(d[3])
        : "r"(a0), "r"(a1), "r"(a2), "r"(a3), "r"(b0), "r"(b1));
}
__device__ __forceinline__ void mma_f16(float* d,
                                        uint32_t a0, uint32_t a1, uint32_t a2, uint32_t a3,
                                        uint32_t b0, uint32_t b1) {
    asm volatile(
        "mma.sync.aligned.m16n8k16.row.col.f32.f16.f16.f32 "
        "{%0,%1,%2,%3}, {%4,%5,%6,%7}, {%8,%9}, {%0,%1,%2,%3};"
        : "+f"(d[0]), "+f"(d[1]), "+f"(d[2]), "+f"(d[3])
        : "r"(a0), "r"(a1), "r"(a2), "r"(a3), "r"(b0), "r"(b1));
}
#define U(x) __float_as_uint(x)
#define CP16(dst, src) \
    asm volatile("cp.async.cg.shared.global [%0], [%1], 16;" :: "r"(dst), "l"(src))
#define CP_COMMIT() asm volatile("cp.async.commit_group;" ::: "memory")
#define CP_WAIT1()  asm volatile("cp.async.wait_group 1;" ::: "memory")
#define CP_WAIT0()  asm volatile("cp.async.wait_group 0;" ::: "memory")
__device__ __forceinline__ uint32_t smem_u32(const void* p) {
    uint32_t a;
    asm("{ .reg .u64 t; cvta.to.shared.u64 t, %1; cvt.u32.u64 %0, t; }"
        : "=r"(a) : "l"(p));
    return a;
}

// ---------------------------------------------------------------------------
// pack_w / pack_x (unchanged)
// ---------------------------------------------------------------------------
__global__ __launch_bounds__(256) void pack_w(const float* __restrict__ W,
                                              uint4* __restrict__ outp, int N) {
    __shared__ float Sw[32 * 136];
    const int t = threadIdx.x;
    const int n0 = blockIdx.x * 128, k0 = blockIdx.y * 32;
    #pragma unroll
    for (int i = 0; i < 4; i++) {
        const int idx = t + i * 256;
        const int kr = idx >> 5, c4 = (idx & 31) * 4;
        *(float4*)&Sw[kr * 136 + c4] =
            *(const float4*)(W + (size_t)(k0 + kr) * N + n0 + c4);
    }
    __syncthreads();
    const size_t ob = ((size_t)blockIdx.x * NCH + blockIdx.y) * 8 * 128;
    #pragma unroll
    for (int i = 0; i < 4; i++) {
        const int idx = t + i * 256;
        const int s = idx >> 7, r = idx & 127;
        const int c0 = (s >> 2) * 16 + 2 * (s & 3), c8 = c0 + 8;
        float h0, l0, h1, l1, h2, l2, h3, l3;
        bsplit(Sw[(c0    ) * 136 + r], h0, l0);
        bsplit(Sw[(c0 + 1) * 136 + r], h1, l1);
        bsplit(Sw[(c8    ) * 136 + r], h2, l2);
        bsplit(Sw[(c8 + 1) * 136 + r], h3, l3);
        outp[ob + s * 128 + r] =
            make_uint4(bpack(h0, h1), bpack(h2, h3), bpack(l0, l1), bpack(l2, l3));
    }
}

__global__ __launch_bounds__(256) void pack_x(const float* __restrict__ A,
                                              uint4* __restrict__ outp) {
    __shared__ float Sx[128 * 36];
    const int t = threadIdx.x;
    const int m0 = blockIdx.x * 128, k0 = blockIdx.y * 32;
    #pragma unroll
    for (int i = 0; i < 4; i++) {
        const int idx = t + i * 256;
        const int row = idx >> 3, c4 = (idx & 7) * 4;
        *(float4*)&Sx[row * 36 + c4] =
            *(const float4*)(A + (size_t)(m0 + row) * KDIM + k0 + c4);
    }
    __syncthreads();
    const size_t ob = ((size_t)blockIdx.x * NCH + blockIdx.y) * 8 * 128;
    #pragma unroll
    for (int i = 0; i < 4; i++) {
        const int idx = t + i * 256;
        const int s = idx >> 7, r = idx & 127;
        const int c0 = (s >> 2) * 16 + 2 * (s & 3), c8 = c0 + 8;
        float h0, l0, h1, l1, h2, l2, h3, l3;
        bsplit(Sx[r * 36 + c0    ], h0, l0);
        bsplit(Sx[r * 36 + c0 + 1], h1, l1);
        bsplit(Sx[r * 36 + c8    ], h2, l2);
        bsplit(Sx[r * 36 + c8 + 1], h3, l3);
        outp[ob + s * 128 + r] =
            make_uint4(bpack(h0, h1), bpack(h2, h3), bpack(l0, l1), bpack(l2, l3));
    }
}

// ---------------------------------------------------------------------------
// 3xBF16 GEMM with fused qkv pack epilogue (R13 — known-good, regs=128)
// ---------------------------------------------------------------------------
#define BRS    130
#define BSTAGE (8*BRS)
#define GSMEM2 (2*2*BSTAGE*16)

__global__ __launch_bounds__(256, 2) void bf16_gemm(
    const uint4* __restrict__ Ap,
    const uint4* __restrict__ Bp,
    const float* __restrict__ bias,
    float* __restrict__ outp, int mode)
{
    extern __shared__ uint4 sm4[];
    const uint32_t sbase = smem_u32(sm4);
    const int t = threadIdx.x, wid = t >> 5, lane = t & 31;
    const int qr = lane >> 2, qc = lane & 3;
    const int m0 = blockIdx.y * 128, n0 = blockIdx.x * 128;
    const int wm = (wid & 3) * 32, wn = (wid >> 2) * 64;

    float acc[2][8][4];
    #pragma unroll
    for (int i = 0; i < 2; i++)
        #pragma unroll
        for (int j = 0; j < 8; j++)
            #pragma unroll
            for (int e = 0; e < 4; e++) acc[i][j][e] = 0.f;

    auto LDST = [&](int c, int st) {
        const uint4* ag = Ap + ((size_t)blockIdx.y * NCH + c) * 8 * 128;
        const uint4* bg = Bp + ((size_t)blockIdx.x * NCH + c) * 8 * 128;
        const uint32_t ab = sbase + (uint32_t)(st * 2 * BSTAGE) * 16;
        const uint32_t bb = ab + (uint32_t)BSTAGE * 16;
        #pragma unroll
        for (int i = 0; i < 4; i++) {
            const int idx = t + i * 256;
            const int slot = idx >> 7, row = idx & 127;
            CP16(ab + (uint32_t)(slot * BRS + row) * 16, ag + idx);
            CP16(bb + (uint32_t)(slot * BRS + row) * 16, bg + idx);
        }
    };
    auto COMPUTE = [&](const uint4* __restrict__ As4, const uint4* __restrict__ Bs4) {
        #pragma unroll
        for (int ks = 0; ks < 2; ks++) {
            uint4 A0[2], A8[2];
            #pragma unroll
            for (int tm = 0; tm < 2; tm++) {
                const int mr = wm + tm * 16 + qr;
                A0[tm] = As4[(ks * 4 + qc) * BRS + mr];
                A8[tm] = As4[(ks * 4 + qc) * BRS + mr + 8];
            }
            #pragma unroll
            for (int tn = 0; tn < 8; tn++) {
                const uint4 Bf = Bs4[(ks * 4 + qc) * BRS + wn + tn * 8 + qr];
                #pragma unroll
                for (int tm = 0; tm < 2; tm++) {
                    float* d = acc[tm][tn];
                    mma_bf16(d, A0[tm].x, A8[tm].x, A0[tm].y, A8[tm].y, Bf.x, Bf.y);
                    mma_bf16(d, A0[tm].x, A8[tm].x, A0[tm].y, A8[tm].y, Bf.z, Bf.w);
                    mma_bf16(d, A0[tm].z, A8[tm].z, A0[tm].w, A8[tm].w, Bf.x, Bf.y);
                }
            }
        }
    };

    LDST(0, 0);
    CP_COMMIT();

    #pragma unroll 1
    for (int c = 0; c < NCH; c += 2) {
        if (c + 1 < NCH) { LDST(c + 1, 1); CP_COMMIT(); CP_WAIT1(); }
        else             { CP_WAIT0(); }
        __syncthreads();
        COMPUTE(sm4, sm4 + BSTAGE);
        __syncthreads();
        if (c + 2 < NCH) { LDST(c + 2, 0); CP_COMMIT(); CP_WAIT1(); }
        else             { CP_WAIT0(); }
        __syncthreads();
        COMPUTE(sm4 + 2 * BSTAGE, sm4 + 3 * BSTAGE);
        __syncthreads();
    }

    if (mode == 1) {
        #pragma unroll
        for (int tm = 0; tm < 2; tm++) {
            const int r0 = m0 + wm + tm * 16 + qr;
            #pragma unroll
            for (int tn = 0; tn < 8; tn++) {
                const int col = n0 + wn + tn * 8 + qc * 2;
                const float bz0 = bias[col], bz1 = bias[col + 1];
                #pragma unroll
                for (int half = 0; half < 2; half++) {
                    const int row = r0 + half * 8;
                    *(float2*)&outp[(size_t)row * DIM + col] =
                        make_float2(acc[tm][tn][half * 2 + 0] + bz0,
                                    acc[tm][tn][half * 2 + 1] + bz1);
                }
            }
        }
        return;
    }

    // mode 0: qkv epilogue with fused flash packing
    const int gc0  = n0 + wn;
    const int h    = gc0 / 192;
    const int part = (gc0 - h * 192) >> 6;

    #pragma unroll
    for (int tm = 0; tm < 2; tm++) {
        const int r0 = m0 + wm + tm * 16 + qr;
        #pragma unroll
        for (int half = 0; half < 2; half++) {
            const int row = r0 + half * 8;
            const int bb = row >> 11, s = row & (SEQ - 1);
            const size_t rowbase = (size_t)(bb * NH + h) * SEQ + s;
            const int e0 = half * 2;
            if (part == 2) {
                #pragma unroll
                for (int tn = 0; tn < 8; tn++) {
                    const int col = gc0 + tn * 8 + qc * 2;
                    const int dd = tn * 8 + qc * 2;
                    *(float2*)&g_v[rowbase * HD + dd] =
                        make_float2(acc[tm][tn][e0] + bias[col],
                                    acc[tm][tn][e0 + 1] + bias[col + 1]);
                }
            } else {
                float sksq = 0.f;
                #pragma unroll
                for (int tn = 0; tn < 8; tn += 2) {
                    const int col = gc0 + tn * 8 + qc * 2;
                    float v0 = acc[tm][tn    ][e0]     + bias[col];
                    float v1 = acc[tm][tn    ][e0 + 1] + bias[col + 1];
                    float v2 = acc[tm][tn + 1][e0]     + bias[col + 8];
                    float v3 = acc[tm][tn + 1][e0 + 1] + bias[col + 9];
                    if (part == 0) {
                        v0 *= C2LE; v1 *= C2LE; v2 *= C2LE; v3 *= C2LE;
                    } else {
                        sksq += v0 * v0 + v1 * v1 + v2 * v2 + v3 * v3;
                    }
                    float h0, l0, h1, l1, h2, l2, h3, l3;
                    bsplit(v0, h0, l0); bsplit(v1, h1, l1);
                    bsplit(v2, h2, l2); bsplit(v3, h3, l3);
                    const uint4 pk = make_uint4(bpack(h0, h1), bpack(h2, h3),
                                                bpack(l0, l1), bpack(l2, l3));
                    const int slot = (tn >> 1) * 4 + qc;
                    if (part == 0) g_qpb[rowbase * 16 + slot] = pk;
                    else           g_kqb[rowbase * 16 + slot] = pk;
                }
                if (part == 1) {
                    sksq += __shfl_xor_sync(0xffffffffu, sksq, 1);
                    sksq += __shfl_xor_sync(0xffffffffu, sksq, 2);
                    if (qc == 0) g_ksq[rowbase] = LOG2E * sksq;
                }
            }
        }
    }
}

// ---------------------------------------------------------------------------
// vpack: g_v floats -> g_vph fp16 key-paired (unchanged)
// ---------------------------------------------------------------------------
#define PSTAGE 68
#define VPACK_SMEM (64*PSTAGE*(int)sizeof(float))

__global__ __launch_bounds__(256) void vpack() {
    extern __shared__ float Sv[];
    const int t = threadIdx.x;
    const int bh = blockIdx.y, s0 = blockIdx.x * 64;
    const size_t base = (size_t)bh * SEQ * HD;

    #pragma unroll
    for (int i = 0; i < 4; i++) {
        const int li = t + i * 256;
        const int row = li >> 4, c4 = (li & 15) << 2;
        *(float4*)&Sv[row * PSTAGE + c4] =
            *(const float4*)(g_v + base + (size_t)(s0 + row) * HD + c4);
    }
    __syncthreads();

    const size_t vb = ((size_t)bh * (SEQ / 64) + (s0 >> 6)) * 2048;
    #pragma unroll
    for (int i = 0; i < 8; i++) {
        const int idx = t + i * 256;
        const int row = idx >> 7;
        const int rem = idx & 127;
        const int d = rem >> 1, which = rem & 1;
        const int ks = row >> 2, qcq = row & 3;
        const int p = ks * 8 + qcq + 4 * which;
        g_vph[vb + idx] = hpack(Sv[(2 * p) * PSTAGE + d], Sv[(2 * p + 1) * PSTAGE + d]);
    }
}

// ---------------------------------------------------------------------------
// Flash attention v8: 128-query CTA (8 warps), double-buffered cp.async
// prefetch of K/V/ksq stages. Arithmetic identical to v7.
// Stage: K 5120 f + V 2176 f + ksq 64 f = 7360 floats (29440 B); x2 stages.
// ---------------------------------------------------------------------------
#define KB4S 20
#define VST  136
#define STG_F  7360
#define STG_B  (STG_F*4)
#define KV_OFF 5120
#define KQ_OFF 7296
#define FLASH_SMEM (2*STG_B)      // 58880 B

__global__ __launch_bounds__(256, 2) void flash_mma() {
    extern __shared__ float s[];
    const uint32_t sbase = smem_u32(s);

    const int t = threadIdx.x, lane = t & 31, w = t >> 5;
    const int qr = lane >> 2, qc = lane & 3;
    const int wm = w * 16;
    const int bh = blockIdx.y;
    const int s0 = blockIdx.x * 128;
    const size_t rbase = (size_t)bh * SEQ;

    // async stage loader (K packed, V fp16-paired, ksq)
    auto load_tile = [&](int t0, int st) {
        const uint32_t kb = sbase + (uint32_t)st * STG_B;
        const uint32_t vb = kb + KV_OFF * 4;
        const uint32_t qb = kb + KQ_OFF * 4;
        const uint4* kg = g_kqb + (rbase + t0) * 16;
        #pragma unroll
        for (int i = 0; i < 4; i++) {
            const int li = t + i * 256;
            const int row = li >> 4, slot = li & 15;
            CP16(kb + (uint32_t)(row * KB4S + slot) * 16, kg + row * 16 + slot);
        }
        const uint4* vg = (const uint4*)g_vph +
                          ((size_t)bh * (SEQ / 64) + (t0 >> 6)) * 512;
        #pragma unroll
        for (int i = 0; i < 2; i++) {
            const int li = t + i * 256;
            const int row = li >> 5, rem = (li & 31) * 4;
            CP16(vb + (uint32_t)(row * VST + rem) * 4, vg + li);
        }
        if (t < 16)
            CP16(qb + t * 16, g_ksq + rbase + t0 + t * 4);
    };

    // Q fragments (loop-invariant)
    uint32_t qh[4][4], ql[4][4];
    {
        const uint4* q0 = g_qpb + (rbase + s0 + wm + qr) * 16;
        const uint4* q1 = q0 + 8 * 16;
        #pragma unroll
        for (int ks = 0; ks < 4; ks++) {
            const uint4 f0 = q0[ks * 4 + qc];
            const uint4 f1 = q1[ks * 4 + qc];
            qh[ks][0] = f0.x; qh[ks][1] = f1.x; qh[ks][2] = f0.y; qh[ks][3] = f1.y;
            ql[ks][0] = f0.z; ql[ks][1] = f1.z; ql[ks][2] = f0.w; ql[ks][3] = f1.w;
        }
    }

    float oacc[8][4];
    #pragma unroll
    for (int tn = 0; tn < 8; tn++)
        #pragma unroll
        for (int e = 0; e < 4; e++) oacc[tn][e] = 0.f;
    float m0r = -1e30f, m1r = -1e30f, l0r = 0.f, l1r = 0.f;

    load_tile(0, 0);
    CP_COMMIT();

    #pragma unroll 1
    for (int it = 0; it < SEQ / 64; it++) {
        const int st = it & 1;
        if (it + 1 < SEQ / 64) {
            load_tile((it + 1) * 64, st ^ 1);
            CP_COMMIT();
            CP_WAIT1();
        } else {
            CP_WAIT0();
        }
        __syncthreads();

        const uint4*    Kb4  = (const uint4*)(s + st * STG_F);
        const uint32_t* Vh   = (const uint32_t*)(s + st * STG_F) + KV_OFF;
        const float*    ksqs = s + st * STG_F + KQ_OFF;

        // S = (2c*Q).K^T — 3xBF16
        float sacc[8][4];
        #pragma unroll
        for (int tn = 0; tn < 8; tn++)
            #pragma unroll
            for (int e = 0; e < 4; e++) sacc[tn][e] = 0.f;

        #pragma unroll
        for (int ks = 0; ks < 4; ks++) {
            #pragma unroll
            for (int tn = 0; tn < 8; tn++) {
                const uint4 wv = Kb4[(tn * 8 + qr) * KB4S + ks * 4 + qc];
                float* d = sacc[tn];
                mma_bf16(d, qh[ks][0], qh[ks][1], qh[ks][2], qh[ks][3], wv.x, wv.y);
                mma_bf16(d, qh[ks][0], qh[ks][1], qh[ks][2], qh[ks][3], wv.z, wv.w);
                mma_bf16(d, ql[ks][0], ql[ks][1], ql[ks][2], ql[ks][3], wv.x, wv.y);
            }
        }

        // online softmax (log2 units)
        float mx0 = -1e30f, mx1 = -1e30f;
        const float2* ksq2 = (const float2*)ksqs;
        #pragma unroll
        for (int tn = 0; tn < 8; tn++) {
            const float2 kk = ksq2[tn * 4 + qc];
            sacc[tn][0] -= kk.x; sacc[tn][1] -= kk.y;
            sacc[tn][2] -= kk.x; sacc[tn][3] -= kk.y;
            mx0 = fmaxf(mx0, fmaxf(sacc[tn][0], sacc[tn][1]));
            mx1 = fmaxf(mx1, fmaxf(sacc[tn][2], sacc[tn][3]));
        }
        #pragma unroll
        for (int off = 1; off <= 2; off <<= 1) {
            mx0 = fmaxf(mx0, __shfl_xor_sync(0xffffffffu, mx0, off));
            mx1 = fmaxf(mx1, __shfl_xor_sync(0xffffffffu, mx1, off));
        }
        const float mn0 = fmaxf(m0r, mx0), mn1 = fmaxf(m1r, mx1);
        const float al0 = ex2f(m0r - mn0), al1 = ex2f(m1r - mn1);
        m0r = mn0; m1r = mn1;

        float rs0 = 0.f, rs1 = 0.f;
        #pragma unroll
        for (int tn = 0; tn < 8; tn++) {
            sacc[tn][0] = ex2f(sacc[tn][0] - mn0);
            sacc[tn][1] = ex2f(sacc[tn][1] - mn0);
            sacc[tn][2] = ex2f(sacc[tn][2] - mn1);
            sacc[tn][3] = ex2f(sacc[tn][3] - mn1);
            rs0 += sacc[tn][0] + sacc[tn][1];
            rs1 += sacc[tn][2] + sacc[tn][3];
            oacc[tn][0] *= al0; oacc[tn][1] *= al0;
            oacc[tn][2] *= al1; oacc[tn][3] *= al1;
        }
        l0r = l0r * al0 + rs0;
        l1r = l1r * al1 + rs1;

        // PV fp16, register-fed
        #pragma unroll
        for (int ks = 0; ks < 4; ks++) {
            const uint32_t a0 = hpack(sacc[2*ks    ][0], sacc[2*ks    ][1]);
            const uint32_t a1 = hpack(sacc[2*ks    ][2], sacc[2*ks    ][3]);
            const uint32_t a2 = hpack(sacc[2*ks + 1][0], sacc[2*ks + 1][1]);
            const uint32_t a3 = hpack(sacc[2*ks + 1][2], sacc[2*ks + 1][3]);
            #pragma unroll
            for (int tn = 0; tn < 8; tn++) {
                const uint2 b01 =
                    *(const uint2*)&Vh[(ks * 4 + qc) * VST + (tn * 8 + qr) * 2];
                mma_f16(oacc[tn], a0, a1, a2, a3, b01.x, b01.y);
            }
        }
        __syncthreads();   // compute on stage st done -> next prefetch may overwrite
    }

    #pragma unroll
    for (int off = 1; off <= 2; off <<= 1) {
        l0r += __shfl_xor_sync(0xffffffffu, l0r, off);
        l1r += __shfl_xor_sync(0xffffffffu, l1r, off);
    }
    const float inv0 = 1.f / l0r, inv1 = 1.f / l1r;
    const int b = bh >> 4, h = bh & 15;

    #pragma unroll
    for (int half = 0; half < 2; half++) {
        const int m = b * SEQ + s0 + wm + qr + half * 8;
        const int mblk = m >> 7, r = m & 127;
        const float inv = half ? inv1 : inv0;
        const int e0 = half * 2;
        #pragma unroll
        for (int tn = 0; tn < 8; tn += 2) {
            const int g = tn * 8 + 2 * qc;
            const int cglob = 2 * h + (g >> 5);
            const int sslot = ((g >> 4) & 1) * 4 + qc;
            float h0, l0, h1, l1, h2, l2, h3, l3;
            bsplit(oacc[tn    ][e0    ] * inv, h0, l0);
            bsplit(oacc[tn    ][e0 + 1] * inv, h1, l1);
            bsplit(oacc[tn + 1][e0    ] * inv, h2, l2);
            bsplit(oacc[tn + 1][e0 + 1] * inv, h3, l3);
            g_attp[((size_t)mblk * NCH + cglob) * 8 * 128 + sslot * 128 + r] =
                make_uint4(bpack(h0, h1), bpack(h2, h3), bpack(l0, l1), bpack(l2, l3));
        }
    }
}

// ---------------------------------------------------------------------------
extern "C" void kernel_launch(void* const* d_in, const int* in_sizes, int n_in,
                              void* d_out, int out_size) {
    (void)in_sizes; (void)n_in; (void)out_size;
    const float* x    = (const float*)d_in[0];
    const float* Wqkv = (const float*)d_in[1];
    const float* bqkv = (const float*)d_in[2];
    const float* Wo   = (const float*)d_in[3];
    const float* bo   = (const float*)d_in[4];
    float*       out  = (float*)d_out;

    uint4* xp;   cudaGetSymbolAddress((void**)&xp,   g_xp);
    uint4* attp; cudaGetSymbolAddress((void**)&attp, g_attp);
    uint4* wqp;  cudaGetSymbolAddress((void**)&wqp,  g_wqp);
    uint4* wop;  cudaGetSymbolAddress((void**)&wop,  g_wop);

    cudaFuncSetAttribute(bf16_gemm, cudaFuncAttributeMaxDynamicSharedMemorySize, GSMEM2);
    cudaFuncSetAttribute(vpack, cudaFuncAttributeMaxDynamicSharedMemorySize, VPACK_SMEM);
    cudaFuncSetAttribute(flash_mma, cudaFuncAttributeMaxDynamicSharedMemorySize, FLASH_SMEM);

    pack_w<<<dim3(N_QKV/128, NCH), 256>>>(Wqkv, wqp, N_QKV);
    pack_w<<<dim3(DIM/128,  NCH), 256>>>(Wo,   wop, DIM);
    pack_x<<<dim3(M_ROWS/128, NCH), 256>>>(x, xp);

    bf16_gemm<<<dim3(N_QKV/128, M_ROWS/128), 256, GSMEM2>>>(xp, wqp, bqkv, nullptr, 0);

    vpack<<<dim3(SEQ/64, NUM_B*NH), 256, VPACK_SMEM>>>();

    flash_mma<<<dim3(SEQ/128, NUM_B*NH), 256, FLASH_SMEM>>>();

    bf16_gemm<<<dim3(DIM/128, M_ROWS/128), 256, GSMEM2>>>(attp, wop, bo, out, 1);
}

// round 16
// speedup vs baseline: 1.1305x; 1.0118x over previous
#include <cuda_runtime.h>
#include <cuda_bf16.h>
#include <cuda_fp16.h>
#include <cstdint>

#define NUM_B 2
#define SEQ   2048
#define DIM   1024
#define NH    16
#define HD    64
#define M_ROWS (NUM_B*SEQ)
#define N_QKV  (3*DIM)
#define KDIM   DIM
#define NCH    (KDIM/32)

#define LOG2E 1.4426950408889634f
#define C2LE  2.8853900817779268f

// bf16 hi/lo fragment-packed GEMM operands
__device__ uint4 g_xp  [(size_t)M_ROWS*256];
__device__ uint4 g_attp[(size_t)M_ROWS*256];
__device__ uint4 g_wqp [(size_t)N_QKV*256];
__device__ uint4 g_wop [(size_t)DIM*256];
// flash operands (all packed directly by qkv epilogue)
__device__ uint4    g_qpb[(size_t)NUM_B*NH*SEQ*16];
__device__ uint4    g_kqb[(size_t)NUM_B*NH*SEQ*16];
__device__ uint32_t g_vph[(size_t)NUM_B*NH*SEQ*32];
__device__ float    g_ksq[(size_t)NUM_B*NH*SEQ];

// ---------------------------------------------------------------------------
// Helpers
// ---------------------------------------------------------------------------
__device__ __forceinline__ float ex2f(float x) {
    float r;
    asm("ex2.approx.f32 %0, %1;" : "=f"(r) : "f"(x));
    return r;
}
__device__ __forceinline__ void bsplit(float x, float& h, float& l) {
    h = __bfloat162float(__float2bfloat16_rn(x));
    l = x - h;
}
__device__ __forceinline__ uint32_t bpack(float a, float b) {
    __nv_bfloat162 t = __floats2bfloat162_rn(a, b);
    return *(uint32_t*)&t;
}
__device__ __forceinline__ uint32_t hpack(float a, float b) {
    __half2 t = __floats2half2_rn(a, b);
    return *(uint32_t*)&t;
}
__device__ __forceinline__ void mma_bf16(float* d,
                                         uint32_t a0, uint32_t a1, uint32_t a2, uint32_t a3,
                                         uint32_t b0, uint32_t b1) {
    asm volatile(
        "mma.sync.aligned.m16n8k16.row.col.f32.bf16.bf16.f32 "
        "{%0,%1,%2,%3}, {%4,%5,%6,%7}, {%8,%9}, {%0,%1,%2,%3};"
        : "+f"(d[0]), "+f"(d[1]), "+f"(d[2]), "+f"(d[3])
        : "r"(a0), "r"(a1), "r"(a2), "r"(a3), "r"(b0), "r"(b1));
}
__device__ __forceinline__ void mma_f16(float* d,
                                        uint32_t a0, uint32_t a1, uint32_t a2, uint32_t a3,
                                        uint32_t b0, uint32_t b1) {
    asm volatile(
        "mma.sync.aligned.m16n8k16.row.col.f32.f16.f16.f32 "
        "{%0,%1,%2,%3}, {%4,%5,%6,%7}, {%8,%9}, {%0,%1,%2,%3};"
        : "+f"(d[0]), "+f"(d[1]), "+f"(d[2]), "+f"(d[3])
        : "r"(a0), "r"(a1), "r"(a2), "r"(a3), "r"(b0), "r"(b1));
}
#define U(x) __float_as_uint(x)
#define CP16(dst, src) \
    asm volatile("cp.async.cg.shared.global [%0], [%1], 16;" :: "r"(dst), "l"(src))
#define CP_COMMIT() asm volatile("cp.async.commit_group;" ::: "memory")
#define CP_WAIT1()  asm volatile("cp.async.wait_group 1;" ::: "memory")
#define CP_WAIT0()  asm volatile("cp.async.wait_group 0;" ::: "memory")
__device__ __forceinline__ uint32_t smem_u32(const void* p) {
    uint32_t a;
    asm("{ .reg .u64 t; cvta.to.shared.u64 t, %1; cvt.u32.u64 %0, t; }"
        : "=r"(a) : "l"(p));
    return a;
}

// ---------------------------------------------------------------------------
// pack_w / pack_x (unchanged)
// ---------------------------------------------------------------------------
__global__ __launch_bounds__(256) void pack_w(const float* __restrict__ W,
                                              uint4* __restrict__ outp, int N) {
    __shared__ float Sw[32 * 136];
    const int t = threadIdx.x;
    const int n0 = blockIdx.x * 128, k0 = blockIdx.y * 32;
    #pragma unroll
    for (int i = 0; i < 4; i++) {
        const int idx = t + i * 256;
        const int kr = idx >> 5, c4 = (idx & 31) * 4;
        *(float4*)&Sw[kr * 136 + c4] =
            *(const float4*)(W + (size_t)(k0 + kr) * N + n0 + c4);
    }
    __syncthreads();
    const size_t ob = ((size_t)blockIdx.x * NCH + blockIdx.y) * 8 * 128;
    #pragma unroll
    for (int i = 0; i < 4; i++) {
        const int idx = t + i * 256;
        const int s = idx >> 7, r = idx & 127;
        const int c0 = (s >> 2) * 16 + 2 * (s & 3), c8 = c0 + 8;
        float h0, l0, h1, l1, h2, l2, h3, l3;
        bsplit(Sw[(c0    ) * 136 + r], h0, l0);
        bsplit(Sw[(c0 + 1) * 136 + r], h1, l1);
        bsplit(Sw[(c8    ) * 136 + r], h2, l2);
        bsplit(Sw[(c8 + 1) * 136 + r], h3, l3);
        outp[ob + s * 128 + r] =
            make_uint4(bpack(h0, h1), bpack(h2, h3), bpack(l0, l1), bpack(l2, l3));
    }
}

__global__ __launch_bounds__(256) void pack_x(const float* __restrict__ A,
                                              uint4* __restrict__ outp) {
    __shared__ float Sx[128 * 36];
    const int t = threadIdx.x;
    const int m0 = blockIdx.x * 128, k0 = blockIdx.y * 32;
    #pragma unroll
    for (int i = 0; i < 4; i++) {
        const int idx = t + i * 256;
        const int row = idx >> 3, c4 = (idx & 7) * 4;
        *(float4*)&Sx[row * 36 + c4] =
            *(const float4*)(A + (size_t)(m0 + row) * KDIM + k0 + c4);
    }
    __syncthreads();
    const size_t ob = ((size_t)blockIdx.x * NCH + blockIdx.y) * 8 * 128;
    #pragma unroll
    for (int i = 0; i < 4; i++) {
        const int idx = t + i * 256;
        const int s = idx >> 7, r = idx & 127;
        const int c0 = (s >> 2) * 16 + 2 * (s & 3), c8 = c0 + 8;
        float h0, l0, h1, l1, h2, l2, h3, l3;
        bsplit(Sx[r * 36 + c0    ], h0, l0);
        bsplit(Sx[r * 36 + c0 + 1], h1, l1);
        bsplit(Sx[r * 36 + c8    ], h2, l2);
        bsplit(Sx[r * 36 + c8 + 1], h3, l3);
        outp[ob + s * 128 + r] =
            make_uint4(bpack(h0, h1), bpack(h2, h3), bpack(l0, l1), bpack(l2, l3));
    }
}

// ---------------------------------------------------------------------------
// 3xBF16 GEMM with fully fused qkv epilogue: q/k fragment packs + ksq + V
// fp16 key-paired pack. FIX vs R15: intra-tile pair index uses (s & 63).
// ---------------------------------------------------------------------------
#define BRS    130
#define BSTAGE (8*BRS)
#define GSMEM2 (2*2*BSTAGE*16)

__global__ __launch_bounds__(256, 2) void bf16_gemm(
    const uint4* __restrict__ Ap,
    const uint4* __restrict__ Bp,
    const float* __restrict__ bias,
    float* __restrict__ outp, int mode)
{
    extern __shared__ uint4 sm4[];
    const uint32_t sbase = smem_u32(sm4);
    const int t = threadIdx.x, wid = t >> 5, lane = t & 31;
    const int qr = lane >> 2, qc = lane & 3;
    const int m0 = blockIdx.y * 128, n0 = blockIdx.x * 128;
    const int wm = (wid & 3) * 32, wn = (wid >> 2) * 64;

    float acc[2][8][4];
    #pragma unroll
    for (int i = 0; i < 2; i++)
        #pragma unroll
        for (int j = 0; j < 8; j++)
            #pragma unroll
            for (int e = 0; e < 4; e++) acc[i][j][e] = 0.f;

    auto LDST = [&](int c, int st) {
        const uint4* ag = Ap + ((size_t)blockIdx.y * NCH + c) * 8 * 128;
        const uint4* bg = Bp + ((size_t)blockIdx.x * NCH + c) * 8 * 128;
        const uint32_t ab = sbase + (uint32_t)(st * 2 * BSTAGE) * 16;
        const uint32_t bb = ab + (uint32_t)BSTAGE * 16;
        #pragma unroll
        for (int i = 0; i < 4; i++) {
            const int idx = t + i * 256;
            const int slot = idx >> 7, row = idx & 127;
            CP16(ab + (uint32_t)(slot * BRS + row) * 16, ag + idx);
            CP16(bb + (uint32_t)(slot * BRS + row) * 16, bg + idx);
        }
    };
    auto COMPUTE = [&](const uint4* __restrict__ As4, const uint4* __restrict__ Bs4) {
        #pragma unroll
        for (int ks = 0; ks < 2; ks++) {
            uint4 A0[2], A8[2];
            #pragma unroll
            for (int tm = 0; tm < 2; tm++) {
                const int mr = wm + tm * 16 + qr;
                A0[tm] = As4[(ks * 4 + qc) * BRS + mr];
                A8[tm] = As4[(ks * 4 + qc) * BRS + mr + 8];
            }
            #pragma unroll
            for (int tn = 0; tn < 8; tn++) {
                const uint4 Bf = Bs4[(ks * 4 + qc) * BRS + wn + tn * 8 + qr];
                #pragma unroll
                for (int tm = 0; tm < 2; tm++) {
                    float* d = acc[tm][tn];
                    mma_bf16(d, A0[tm].x, A8[tm].x, A0[tm].y, A8[tm].y, Bf.x, Bf.y);
                    mma_bf16(d, A0[tm].x, A8[tm].x, A0[tm].y, A8[tm].y, Bf.z, Bf.w);
                    mma_bf16(d, A0[tm].z, A8[tm].z, A0[tm].w, A8[tm].w, Bf.x, Bf.y);
                }
            }
        }
    };

    LDST(0, 0);
    CP_COMMIT();

    #pragma unroll 1
    for (int c = 0; c < NCH; c += 2) {
        if (c + 1 < NCH) { LDST(c + 1, 1); CP_COMMIT(); CP_WAIT1(); }
        else             { CP_WAIT0(); }
        __syncthreads();
        COMPUTE(sm4, sm4 + BSTAGE);
        __syncthreads();
        if (c + 2 < NCH) { LDST(c + 2, 0); CP_COMMIT(); CP_WAIT1(); }
        else             { CP_WAIT0(); }
        __syncthreads();
        COMPUTE(sm4 + 2 * BSTAGE, sm4 + 3 * BSTAGE);
        __syncthreads();
    }

    if (mode == 1) {
        #pragma unroll
        for (int tm = 0; tm < 2; tm++) {
            const int r0 = m0 + wm + tm * 16 + qr;
            #pragma unroll
            for (int tn = 0; tn < 8; tn++) {
                const int col = n0 + wn + tn * 8 + qc * 2;
                const float bz0 = bias[col], bz1 = bias[col + 1];
                #pragma unroll
                for (int half = 0; half < 2; half++) {
                    const int row = r0 + half * 8;
                    *(float2*)&outp[(size_t)row * DIM + col] =
                        make_float2(acc[tm][tn][half * 2 + 0] + bz0,
                                    acc[tm][tn][half * 2 + 1] + bz1);
                }
            }
        }
        return;
    }

    // mode 0: qkv epilogue with fused q/k/v flash packing
    const int gc0  = n0 + wn;
    const int h    = gc0 / 192;
    const int part = (gc0 - h * 192) >> 6;

    #pragma unroll
    for (int tm = 0; tm < 2; tm++) {
        const int r0 = m0 + wm + tm * 16 + qr;
        #pragma unroll
        for (int half = 0; half < 2; half++) {
            const int row = r0 + half * 8;
            const int bb = row >> 11, s = row & (SEQ - 1);
            const size_t rowbase = (size_t)(bb * NH + h) * SEQ + s;
            const int e0 = half * 2;
            if (part == 2) {
                // V: pair adjacent seq rows via shuffle, emit fp16 key-paired
                // layout. Intra-tile pair index (FIXED: use s & 63).
                const int p = (s & 63) >> 1;
                const int ks4 = p >> 3, which = (p >> 2) & 1, qcv = p & 3;
                const size_t vb = ((size_t)(bb * NH + h) * (SEQ / 64) + (s >> 6)) * 2048
                                  + (size_t)(ks4 * 4 + qcv) * 128 + which;
                #pragma unroll
                for (int tn = 0; tn < 8; tn++) {
                    const int col = gc0 + tn * 8 + qc * 2;
                    const int d0 = tn * 8 + qc * 2;
                    const float v0 = acc[tm][tn][e0]     + bias[col];
                    const float v1 = acc[tm][tn][e0 + 1] + bias[col + 1];
                    const float p0 = __shfl_down_sync(0xffffffffu, v0, 4);
                    const float p1 = __shfl_down_sync(0xffffffffu, v1, 4);
                    if (!(qr & 1)) {
                        g_vph[vb + 2 * d0]     = hpack(v0, p0);
                        g_vph[vb + 2 * d0 + 2] = hpack(v1, p1);
                    }
                }
            } else {
                float sksq = 0.f;
                #pragma unroll
                for (int tn = 0; tn < 8; tn += 2) {
                    const int col = gc0 + tn * 8 + qc * 2;
                    float v0 = acc[tm][tn    ][e0]     + bias[col];
                    float v1 = acc[tm][tn    ][e0 + 1] + bias[col + 1];
                    float v2 = acc[tm][tn + 1][e0]     + bias[col + 8];
                    float v3 = acc[tm][tn + 1][e0 + 1] + bias[col + 9];
                    if (part == 0) {
                        v0 *= C2LE; v1 *= C2LE; v2 *= C2LE; v3 *= C2LE;
                    } else {
                        sksq += v0 * v0 + v1 * v1 + v2 * v2 + v3 * v3;
                    }
                    float h0, l0, h1, l1, h2, l2, h3, l3;
                    bsplit(v0, h0, l0); bsplit(v1, h1, l1);
                    bsplit(v2, h2, l2); bsplit(v3, h3, l3);
                    const uint4 pk = make_uint4(bpack(h0, h1), bpack(h2, h3),
                                                bpack(l0, l1), bpack(l2, l3));
                    const int slot = (tn >> 1) * 4 + qc;
                    if (part == 0) g_qpb[rowbase * 16 + slot] = pk;
                    else           g_kqb[rowbase * 16 + slot] = pk;
                }
                if (part == 1) {
                    sksq += __shfl_xor_sync(0xffffffffu, sksq, 1);
                    sksq += __shfl_xor_sync(0xffffffffu, sksq, 2);
                    if (qc == 0) g_ksq[rowbase] = LOG2E * sksq;
                }
            }
        }
    }
}

// ---------------------------------------------------------------------------
// Flash attention v8 (unchanged from R14 — known-good)
// ---------------------------------------------------------------------------
#define KB4S 20
#define VST  136
#define STG_F  7360
#define STG_B  (STG_F*4)
#define KV_OFF 5120
#define KQ_OFF 7296
#define FLASH_SMEM (2*STG_B)

__global__ __launch_bounds__(256, 2) void flash_mma() {
    extern __shared__ float s[];
    const uint32_t sbase = smem_u32(s);

    const int t = threadIdx.x, lane = t & 31, w = t >> 5;
    const int qr = lane >> 2, qc = lane & 3;
    const int wm = w * 16;
    const int bh = blockIdx.y;
    const int s0 = blockIdx.x * 128;
    const size_t rbase = (size_t)bh * SEQ;

    auto load_tile = [&](int t0, int st) {
        const uint32_t kb = sbase + (uint32_t)st * STG_B;
        const uint32_t vb = kb + KV_OFF * 4;
        const uint32_t qb = kb + KQ_OFF * 4;
        const uint4* kg = g_kqb + (rbase + t0) * 16;
        #pragma unroll
        for (int i = 0; i < 4; i++) {
            const int li = t + i * 256;
            const int row = li >> 4, slot = li & 15;
            CP16(kb + (uint32_t)(row * KB4S + slot) * 16, kg + row * 16 + slot);
        }
        const uint4* vg = (const uint4*)g_vph +
                          ((size_t)bh * (SEQ / 64) + (t0 >> 6)) * 512;
        #pragma unroll
        for (int i = 0; i < 2; i++) {
            const int li = t + i * 256;
            const int row = li >> 5, rem = (li & 31) * 4;
            CP16(vb + (uint32_t)(row * VST + rem) * 4, vg + li);
        }
        if (t < 16)
            CP16(qb + t * 16, g_ksq + rbase + t0 + t * 4);
    };

    uint32_t qh[4][4], ql[4][4];
    {
        const uint4* q0 = g_qpb + (rbase + s0 + wm + qr) * 16;
        const uint4* q1 = q0 + 8 * 16;
        #pragma unroll
        for (int ks = 0; ks < 4; ks++) {
            const uint4 f0 = q0[ks * 4 + qc];
            const uint4 f1 = q1[ks * 4 + qc];
            qh[ks][0] = f0.x; qh[ks][1] = f1.x; qh[ks][2] = f0.y; qh[ks][3] = f1.y;
            ql[ks][0] = f0.z; ql[ks][1] = f1.z; ql[ks][2] = f0.w; ql[ks][3] = f1.w;
        }
    }

    float oacc[8][4];
    #pragma unroll
    for (int tn = 0; tn < 8; tn++)
        #pragma unroll
        for (int e = 0; e < 4; e++) oacc[tn][e] = 0.f;
    float m0r = -1e30f, m1r = -1e30f, l0r = 0.f, l1r = 0.f;

    load_tile(0, 0);
    CP_COMMIT();

    #pragma unroll 1
    for (int it = 0; it < SEQ / 64; it++) {
        const int st = it & 1;
        if (it + 1 < SEQ / 64) {
            load_tile((it + 1) * 64, st ^ 1);
            CP_COMMIT();
            CP_WAIT1();
        } else {
            CP_WAIT0();
        }
        __syncthreads();

        const uint4*    Kb4  = (const uint4*)(s + st * STG_F);
        const uint32_t* Vh   = (const uint32_t*)(s + st * STG_F) + KV_OFF;
        const float*    ksqs = s + st * STG_F + KQ_OFF;

        float sacc[8][4];
        #pragma unroll
        for (int tn = 0; tn < 8; tn++)
            #pragma unroll
            for (int e = 0; e < 4; e++) sacc[tn][e] = 0.f;

        #pragma unroll
        for (int ks = 0; ks < 4; ks++) {
            #pragma unroll
            for (int tn = 0; tn < 8; tn++) {
                const uint4 wv = Kb4[(tn * 8 + qr) * KB4S + ks * 4 + qc];
                float* d = sacc[tn];
                mma_bf16(d, qh[ks][0], qh[ks][1], qh[ks][2], qh[ks][3], wv.x, wv.y);
                mma_bf16(d, qh[ks][0], qh[ks][1], qh[ks][2], qh[ks][3], wv.z, wv.w);
                mma_bf16(d, ql[ks][0], ql[ks][1], ql[ks][2], ql[ks][3], wv.x, wv.y);
            }
        }

        float mx0 = -1e30f, mx1 = -1e30f;
        const float2* ksq2 = (const float2*)ksqs;
        #pragma unroll
        for (int tn = 0; tn < 8; tn++) {
            const float2 kk = ksq2[tn * 4 + qc];
            sacc[tn][0] -= kk.x; sacc[tn][1] -= kk.y;
            sacc[tn][2] -= kk.x; sacc[tn][3] -= kk.y;
            mx0 = fmaxf(mx0, fmaxf(sacc[tn][0], sacc[tn][1]));
            mx1 = fmaxf(mx1, fmaxf(sacc[tn][2], sacc[tn][3]));
        }
        #pragma unroll
        for (int off = 1; off <= 2; off <<= 1) {
            mx0 = fmaxf(mx0, __shfl_xor_sync(0xffffffffu, mx0, off));
            mx1 = fmaxf(mx1, __shfl_xor_sync(0xffffffffu, mx1, off));
        }
        const float mn0 = fmaxf(m0r, mx0), mn1 = fmaxf(m1r, mx1);
        const float al0 = ex2f(m0r - mn0), al1 = ex2f(m1r - mn1);
        m0r = mn0; m1r = mn1;

        float rs0 = 0.f, rs1 = 0.f;
        #pragma unroll
        for (int tn = 0; tn < 8; tn++) {
            sacc[tn][0] = ex2f(sacc[tn][0] - mn0);
            sacc[tn][1] = ex2f(sacc[tn][1] - mn0);
            sacc[tn][2] = ex2f(sacc[tn][2] - mn1);
            sacc[tn][3] = ex2f(sacc[tn][3] - mn1);
            rs0 += sacc[tn][0] + sacc[tn][1];
            rs1 += sacc[tn][2] + sacc[tn][3];
            oacc[tn][0] *= al0; oacc[tn][1] *= al0;
            oacc[tn][2] *= al1; oacc[tn][3] *= al1;
        }
        l0r = l0r * al0 + rs0;
        l1r = l1r * al1 + rs1;

        #pragma unroll
        for (int ks = 0; ks < 4; ks++) {
            const uint32_t a0 = hpack(sacc[2*ks    ][0], sacc[2*ks    ][1]);
            const uint32_t a1 = hpack(sacc[2*ks    ][2], sacc[2*ks    ][3]);
            const uint32_t a2 = hpack(sacc[2*ks + 1][0], sacc[2*ks + 1][1]);
            const uint32_t a3 = hpack(sacc[2*ks + 1][2], sacc[2*ks + 1][3]);
            #pragma unroll
            for (int tn = 0; tn < 8; tn++) {
                const uint2 b01 =
                    *(const uint2*)&Vh[(ks * 4 + qc) * VST + (tn * 8 + qr) * 2];
                mma_f16(oacc[tn], a0, a1, a2, a3, b01.x, b01.y);
            }
        }
        __syncthreads();
    }

    #pragma unroll
    for (int off = 1; off <= 2; off <<= 1) {
        l0r += __shfl_xor_sync(0xffffffffu, l0r, off);
        l1r += __shfl_xor_sync(0xffffffffu, l1r, off);
    }
    const float inv0 = 1.f / l0r, inv1 = 1.f / l1r;
    const int b = bh >> 4, h = bh & 15;

    #pragma unroll
    for (int half = 0; half < 2; half++) {
        const int m = b * SEQ + s0 + wm + qr + half * 8;
        const int mblk = m >> 7, r = m & 127;
        const float inv = half ? inv1 : inv0;
        const int e0 = half * 2;
        #pragma unroll
        for (int tn = 0; tn < 8; tn += 2) {
            const int g = tn * 8 + 2 * qc;
            const int cglob = 2 * h + (g >> 5);
            const int sslot = ((g >> 4) & 1) * 4 + qc;
            float h0, l0, h1, l1, h2, l2, h3, l3;
            bsplit(oacc[tn    ][e0    ] * inv, h0, l0);
            bsplit(oacc[tn    ][e0 + 1] * inv, h1, l1);
            bsplit(oacc[tn + 1][e0    ] * inv, h2, l2);
            bsplit(oacc[tn + 1][e0 + 1] * inv, h3, l3);
            g_attp[((size_t)mblk * NCH + cglob) * 8 * 128 + sslot * 128 + r] =
                make_uint4(bpack(h0, h1), bpack(h2, h3), bpack(l0, l1), bpack(l2, l3));
        }
    }
}

// ---------------------------------------------------------------------------
extern "C" void kernel_launch(void* const* d_in, const int* in_sizes, int n_in,
                              void* d_out, int out_size) {
    (void)in_sizes; (void)n_in; (void)out_size;
    const float* x    = (const float*)d_in[0];
    const float* Wqkv = (const float*)d_in[1];
    const float* bqkv = (const float*)d_in[2];
    const float* Wo   = (const float*)d_in[3];
    const float* bo   = (const float*)d_in[4];
    float*       out  = (float*)d_out;

    uint4* xp;   cudaGetSymbolAddress((void**)&xp,   g_xp);
    uint4* attp; cudaGetSymbolAddress((void**)&attp, g_attp);
    uint4* wqp;  cudaGetSymbolAddress((void**)&wqp,  g_wqp);
    uint4* wop;  cudaGetSymbolAddress((void**)&wop,  g_wop);

    cudaFuncSetAttribute(bf16_gemm, cudaFuncAttributeMaxDynamicSharedMemorySize, GSMEM2);
    cudaFuncSetAttribute(flash_mma, cudaFuncAttributeMaxDynamicSharedMemorySize, FLASH_SMEM);

    pack_w<<<dim3(N_QKV/128, NCH), 256>>>(Wqkv, wqp, N_QKV);
    pack_w<<<dim3(DIM/128,  NCH), 256>>>(Wo,   wop, DIM);
    pack_x<<<dim3(M_ROWS/128, NCH), 256>>>(x, xp);

    bf16_gemm<<<dim3(N_QKV/128, M_ROWS/128), 256, GSMEM2>>>(xp, wqp, bqkv, nullptr, 0);

    flash_mma<<<dim3(SEQ/128, NUM_B*NH), 256, FLASH_SMEM>>>();

    bf16_gemm<<<dim3(DIM/128, M_ROWS/128), 256, GSMEM2>>>(attp, wop, bo, out, 1);
}

// round 17
// speedup vs baseline: 1.1550x; 1.0216x over previous
#include <cuda_runtime.h>
#include <cuda_bf16.h>
#include <cuda_fp16.h>
#include <cstdint>

#define NUM_B 2
#define SEQ   2048
#define DIM   1024
#define NH    16
#define HD    64
#define M_ROWS (NUM_B*SEQ)
#define N_QKV  (3*DIM)
#define KDIM   DIM
#define NCH    (KDIM/32)

#define LOG2E 1.4426950408889634f
#define C2LE  2.8853900817779268f

// bf16 hi/lo fragment-packed GEMM operands
__device__ uint4 g_xp  [(size_t)M_ROWS*256];
__device__ uint4 g_attp[(size_t)M_ROWS*256];
__device__ uint4 g_wqp [(size_t)N_QKV*256];
__device__ uint4 g_wop [(size_t)DIM*256];
// flash operands (all packed directly by qkv epilogue)
__device__ uint4    g_qpb[(size_t)NUM_B*NH*SEQ*16];
__device__ uint4    g_kqb[(size_t)NUM_B*NH*SEQ*16];
__device__ uint32_t g_vph[(size_t)NUM_B*NH*SEQ*32];
__device__ float    g_ksq[(size_t)NUM_B*NH*SEQ];

// ---------------------------------------------------------------------------
// Helpers
// ---------------------------------------------------------------------------
__device__ __forceinline__ float ex2f(float x) {
    float r;
    asm("ex2.approx.f32 %0, %1;" : "=f"(r) : "f"(x));
    return r;
}
__device__ __forceinline__ void bsplit(float x, float& h, float& l) {
    h = __bfloat162float(__float2bfloat16_rn(x));
    l = x - h;
}
__device__ __forceinline__ uint32_t bpack(float a, float b) {
    __nv_bfloat162 t = __floats2bfloat162_rn(a, b);
    return *(uint32_t*)&t;
}
__device__ __forceinline__ uint32_t hpack(float a, float b) {
    __half2 t = __floats2half2_rn(a, b);
    return *(uint32_t*)&t;
}
__device__ __forceinline__ void mma_bf16(float* d,
                                         uint32_t a0, uint32_t a1, uint32_t a2, uint32_t a3,
                                         uint32_t b0, uint32_t b1) {
    asm volatile(
        "mma.sync.aligned.m16n8k16.row.col.f32.bf16.bf16.f32 "
        "{%0,%1,%2,%3}, {%4,%5,%6,%7}, {%8,%9}, {%0,%1,%2,%3};"
        : "+f"(d[0]), "+f"(d[1]), "+f"(d[2]), "+f"(d[3])
        : "r"(a0), "r"(a1), "r"(a2), "r"(a3), "r"(b0), "r"(b1));
}
__device__ __forceinline__ void mma_f16(float* d,
                                        uint32_t a0, uint32_t a1, uint32_t a2, uint32_t a3,
                                        uint32_t b0, uint32_t b1) {
    asm volatile(
        "mma.sync.aligned.m16n8k16.row.col.f32.f16.f16.f32 "
        "{%0,%1,%2,%3}, {%4,%5,%6,%7}, {%8,%9}, {%0,%1,%2,%3};"
        : "+f"(d[0]), "+f"(d[1]), "+f"(d[2]), "+f"(d[3])
        : "r"(a0), "r"(a1), "r"(a2), "r"(a3), "r"(b0), "r"(b1));
}
#define U(x) __float_as_uint(x)
#define CP16(dst, src) \
    asm volatile("cp.async.cg.shared.global [%0], [%1], 16;" :: "r"(dst), "l"(src))
#define CP_COMMIT() asm volatile("cp.async.commit_group;" ::: "memory")
#define CP_WAIT1()  asm volatile("cp.async.wait_group 1;" ::: "memory")
#define CP_WAIT0()  asm volatile("cp.async.wait_group 0;" ::: "memory")
__device__ __forceinline__ uint32_t smem_u32(const void* p) {
    uint32_t a;
    asm("{ .reg .u64 t; cvta.to.shared.u64 t, %1; cvt.u32.u64 %0, t; }"
        : "=r"(a) : "l"(p));
    return a;
}

// ---------------------------------------------------------------------------
// pack_all: one launch packs W_qkv (cols 0..23), W_o (24..31), x (32..63).
// ---------------------------------------------------------------------------
__global__ __launch_bounds__(256) void pack_all(const float* __restrict__ x,
                                                const float* __restrict__ Wqkv,
                                                const float* __restrict__ Wo) {
    __shared__ float S[128 * 36];   // max of both staging needs (18432 B)
    const int t = threadIdx.x;
    const int bx = blockIdx.x, k0 = blockIdx.y * 32;

    if (bx < 32) {
        // weight pack: W [KDIM][N] -> [nblk][c][s][r]
        const float* W = (bx < 24) ? Wqkv : Wo;
        uint4* outp    = (bx < 24) ? g_wqp : g_wop;
        const int N    = (bx < 24) ? N_QKV : DIM;
        const int cb   = (bx < 24) ? bx : bx - 24;
        const int n0   = cb * 128;
        #pragma unroll
        for (int i = 0; i < 4; i++) {
            const int idx = t + i * 256;
            const int kr = idx >> 5, c4 = (idx & 31) * 4;
            *(float4*)&S[kr * 136 + c4] =
                *(const float4*)(W + (size_t)(k0 + kr) * N + n0 + c4);
        }
        __syncthreads();
        const size_t ob = ((size_t)cb * NCH + blockIdx.y) * 8 * 128;
        #pragma unroll
        for (int i = 0; i < 4; i++) {
            const int idx = t + i * 256;
            const int s = idx >> 7, r = idx & 127;
            const int c0 = (s >> 2) * 16 + 2 * (s & 3), c8 = c0 + 8;
            float h0, l0, h1, l1, h2, l2, h3, l3;
            bsplit(S[(c0    ) * 136 + r], h0, l0);
            bsplit(S[(c0 + 1) * 136 + r], h1, l1);
            bsplit(S[(c8    ) * 136 + r], h2, l2);
            bsplit(S[(c8 + 1) * 136 + r], h3, l3);
            outp[ob + s * 128 + r] =
                make_uint4(bpack(h0, h1), bpack(h2, h3), bpack(l0, l1), bpack(l2, l3));
        }
    } else {
        // x pack: A [M][K] row-major -> [mblk][c][s][r]
        const int mb = bx - 32;
        const int m0 = mb * 128;
        #pragma unroll
        for (int i = 0; i < 4; i++) {
            const int idx = t + i * 256;
            const int row = idx >> 3, c4 = (idx & 7) * 4;
            *(float4*)&S[row * 36 + c4] =
                *(const float4*)(x + (size_t)(m0 + row) * KDIM + k0 + c4);
        }
        __syncthreads();
        const size_t ob = ((size_t)mb * NCH + blockIdx.y) * 8 * 128;
        #pragma unroll
        for (int i = 0; i < 4; i++) {
            const int idx = t + i * 256;
            const int s = idx >> 7, r = idx & 127;
            const int c0 = (s >> 2) * 16 + 2 * (s & 3), c8 = c0 + 8;
            float h0, l0, h1, l1, h2, l2, h3, l3;
            bsplit(S[r * 36 + c0    ], h0, l0);
            bsplit(S[r * 36 + c0 + 1], h1, l1);
            bsplit(S[r * 36 + c8    ], h2, l2);
            bsplit(S[r * 36 + c8 + 1], h3, l3);
            g_xp[ob + s * 128 + r] =
                make_uint4(bpack(h0, h1), bpack(h2, h3), bpack(l0, l1), bpack(l2, l3));
        }
    }
}

// ---------------------------------------------------------------------------
// 3xBF16 GEMM v4: 64x128 CTA tile, 4 warps (warp tile 32x64 — identical
// per-warp inner loop to R10/R13), 4 CTAs/SM. Finer wave granularity
// halves the last-wave tail. Fused qkv pack epilogue retained.
// A smem stride 66 uint4 (66 mod 8 = 2 -> fragment banks 2qc+qr distinct).
// ---------------------------------------------------------------------------
#define A_SL   66
#define A_SZ   (8*A_SL)           // 528 uint4
#define B_SL   130
#define B_SZ   (8*B_SL)           // 1040 uint4
#define STG    (A_SZ + B_SZ)      // 1568 uint4 per stage
#define GSMEM2 (2*STG*16)         // 50176 B

__global__ __launch_bounds__(128, 4) void bf16_gemm(
    const uint4* __restrict__ Ap,
    const uint4* __restrict__ Bp,
    const float* __restrict__ bias,
    float* __restrict__ outp, int mode)
{
    extern __shared__ uint4 sm4[];
    const uint32_t sbase = smem_u32(sm4);
    const int t = threadIdx.x, wid = t >> 5, lane = t & 31;
    const int qr = lane >> 2, qc = lane & 3;
    const int m0 = blockIdx.y * 64, n0 = blockIdx.x * 128;
    const int wm = (wid & 1) * 32, wn = (wid >> 1) * 64;
    const int mblk = m0 >> 7, rowoff = m0 & 127;

    float acc[2][8][4];
    #pragma unroll
    for (int i = 0; i < 2; i++)
        #pragma unroll
        for (int j = 0; j < 8; j++)
            #pragma unroll
            for (int e = 0; e < 4; e++) acc[i][j][e] = 0.f;

    auto LDST = [&](int c, int st) {
        const uint4* ag = Ap + ((size_t)mblk * NCH + c) * 1024 + rowoff;
        const uint4* bg = Bp + ((size_t)blockIdx.x * NCH + c) * 1024;
        const uint32_t ab = sbase + (uint32_t)(st * STG) * 16;
        const uint32_t bb = ab + (uint32_t)A_SZ * 16;
        #pragma unroll
        for (int i = 0; i < 4; i++) {             // A: 8 slots x 64 rows
            const int idx = t + i * 128;
            const int slot = idx >> 6, row = idx & 63;
            CP16(ab + (uint32_t)(slot * A_SL + row) * 16, ag + slot * 128 + row);
        }
        #pragma unroll
        for (int i = 0; i < 8; i++) {             // B: 8 slots x 128 rows
            const int idx = t + i * 128;
            const int slot = idx >> 7, row = idx & 127;
            CP16(bb + (uint32_t)(slot * B_SL + row) * 16, bg + idx);
        }
    };
    auto COMPUTE = [&](const uint4* __restrict__ As4, const uint4* __restrict__ Bs4) {
        #pragma unroll
        for (int ks = 0; ks < 2; ks++) {
            uint4 A0[2], A8[2];
            #pragma unroll
            for (int tm = 0; tm < 2; tm++) {
                const int mr = wm + tm * 16 + qr;
                A0[tm] = As4[(ks * 4 + qc) * A_SL + mr];
                A8[tm] = As4[(ks * 4 + qc) * A_SL + mr + 8];
            }
            #pragma unroll
            for (int tn = 0; tn < 8; tn++) {
                const uint4 Bf = Bs4[(ks * 4 + qc) * B_SL + wn + tn * 8 + qr];
                #pragma unroll
                for (int tm = 0; tm < 2; tm++) {
                    float* d = acc[tm][tn];
                    mma_bf16(d, A0[tm].x, A8[tm].x, A0[tm].y, A8[tm].y, Bf.x, Bf.y);
                    mma_bf16(d, A0[tm].x, A8[tm].x, A0[tm].y, A8[tm].y, Bf.z, Bf.w);
                    mma_bf16(d, A0[tm].z, A8[tm].z, A0[tm].w, A8[tm].w, Bf.x, Bf.y);
                }
            }
        }
    };

    LDST(0, 0);
    CP_COMMIT();

    #pragma unroll 1
    for (int c = 0; c < NCH; c += 2) {
        if (c + 1 < NCH) { LDST(c + 1, 1); CP_COMMIT(); CP_WAIT1(); }
        else             { CP_WAIT0(); }
        __syncthreads();
        COMPUTE(sm4, sm4 + A_SZ);
        __syncthreads();
        if (c + 2 < NCH) { LDST(c + 2, 0); CP_COMMIT(); CP_WAIT1(); }
        else             { CP_WAIT0(); }
        __syncthreads();
        COMPUTE(sm4 + STG, sm4 + STG + A_SZ);
        __syncthreads();
    }

    if (mode == 1) {
        #pragma unroll
        for (int tm = 0; tm < 2; tm++) {
            const int r0 = m0 + wm + tm * 16 + qr;
            #pragma unroll
            for (int tn = 0; tn < 8; tn++) {
                const int col = n0 + wn + tn * 8 + qc * 2;
                const float bz0 = bias[col], bz1 = bias[col + 1];
                #pragma unroll
                for (int half = 0; half < 2; half++) {
                    const int row = r0 + half * 8;
                    *(float2*)&outp[(size_t)row * DIM + col] =
                        make_float2(acc[tm][tn][half * 2 + 0] + bz0,
                                    acc[tm][tn][half * 2 + 1] + bz1);
                }
            }
        }
        return;
    }

    // mode 0: qkv epilogue with fused q/k/v flash packing
    const int gc0  = n0 + wn;
    const int h    = gc0 / 192;
    const int part = (gc0 - h * 192) >> 6;

    #pragma unroll
    for (int tm = 0; tm < 2; tm++) {
        const int r0 = m0 + wm + tm * 16 + qr;
        #pragma unroll
        for (int half = 0; half < 2; half++) {
            const int row = r0 + half * 8;
            const int bb = row >> 11, s = row & (SEQ - 1);
            const size_t rowbase = (size_t)(bb * NH + h) * SEQ + s;
            const int e0 = half * 2;
            if (part == 2) {
                const int p = (s & 63) >> 1;
                const int ks4 = p >> 3, which = (p >> 2) & 1, qcv = p & 3;
                const size_t vb = ((size_t)(bb * NH + h) * (SEQ / 64) + (s >> 6)) * 2048
                                  + (size_t)(ks4 * 4 + qcv) * 128 + which;
                #pragma unroll
                for (int tn = 0; tn < 8; tn++) {
                    const int col = gc0 + tn * 8 + qc * 2;
                    const int d0 = tn * 8 + qc * 2;
                    const float v0 = acc[tm][tn][e0]     + bias[col];
                    const float v1 = acc[tm][tn][e0 + 1] + bias[col + 1];
                    const float p0 = __shfl_down_sync(0xffffffffu, v0, 4);
                    const float p1 = __shfl_down_sync(0xffffffffu, v1, 4);
                    if (!(qr & 1)) {
                        g_vph[vb + 2 * d0]     = hpack(v0, p0);
                        g_vph[vb + 2 * d0 + 2] = hpack(v1, p1);
                    }
                }
            } else {
                float sksq = 0.f;
                #pragma unroll
                for (int tn = 0; tn < 8; tn += 2) {
                    const int col = gc0 + tn * 8 + qc * 2;
                    float v0 = acc[tm][tn    ][e0]     + bias[col];
                    float v1 = acc[tm][tn    ][e0 + 1] + bias[col + 1];
                    float v2 = acc[tm][tn + 1][e0]     + bias[col + 8];
                    float v3 = acc[tm][tn + 1][e0 + 1] + bias[col + 9];
                    if (part == 0) {
                        v0 *= C2LE; v1 *= C2LE; v2 *= C2LE; v3 *= C2LE;
                    } else {
                        sksq += v0 * v0 + v1 * v1 + v2 * v2 + v3 * v3;
                    }
                    float h0, l0, h1, l1, h2, l2, h3, l3;
                    bsplit(v0, h0, l0); bsplit(v1, h1, l1);
                    bsplit(v2, h2, l2); bsplit(v3, h3, l3);
                    const uint4 pk = make_uint4(bpack(h0, h1), bpack(h2, h3),
                                                bpack(l0, l1), bpack(l2, l3));
                    const int slot = (tn >> 1) * 4 + qc;
                    if (part == 0) g_qpb[rowbase * 16 + slot] = pk;
                    else           g_kqb[rowbase * 16 + slot] = pk;
                }
                if (part == 1) {
                    sksq += __shfl_xor_sync(0xffffffffu, sksq, 1);
                    sksq += __shfl_xor_sync(0xffffffffu, sksq, 2);
                    if (qc == 0) g_ksq[rowbase] = LOG2E * sksq;
                }
            }
        }
    }
}

// ---------------------------------------------------------------------------
// Flash attention v8 (unchanged — known-good)
// ---------------------------------------------------------------------------
#define KB4S 20
#define VST  136
#define STG_F  7360
#define STG_B  (STG_F*4)
#define KV_OFF 5120
#define KQ_OFF 7296
#define FLASH_SMEM (2*STG_B)

__global__ __launch_bounds__(256, 2) void flash_mma() {
    extern __shared__ float s[];
    const uint32_t sbase = smem_u32(s);

    const int t = threadIdx.x, lane = t & 31, w = t >> 5;
    const int qr = lane >> 2, qc = lane & 3;
    const int wm = w * 16;
    const int bh = blockIdx.y;
    const int s0 = blockIdx.x * 128;
    const size_t rbase = (size_t)bh * SEQ;

    auto load_tile = [&](int t0, int st) {
        const uint32_t kb = sbase + (uint32_t)st * STG_B;
        const uint32_t vb = kb + KV_OFF * 4;
        const uint32_t qb = kb + KQ_OFF * 4;
        const uint4* kg = g_kqb + (rbase + t0) * 16;
        #pragma unroll
        for (int i = 0; i < 4; i++) {
            const int li = t + i * 256;
            const int row = li >> 4, slot = li & 15;
            CP16(kb + (uint32_t)(row * KB4S + slot) * 16, kg + row * 16 + slot);
        }
        const uint4* vg = (const uint4*)g_vph +
                          ((size_t)bh * (SEQ / 64) + (t0 >> 6)) * 512;
        #pragma unroll
        for (int i = 0; i < 2; i++) {
            const int li = t + i * 256;
            const int row = li >> 5, rem = (li & 31) * 4;
            CP16(vb + (uint32_t)(row * VST + rem) * 4, vg + li);
        }
        if (t < 16)
            CP16(qb + t * 16, g_ksq + rbase + t0 + t * 4);
    };

    uint32_t qh[4][4], ql[4][4];
    {
        const uint4* q0 = g_qpb + (rbase + s0 + wm + qr) * 16;
        const uint4* q1 = q0 + 8 * 16;
        #pragma unroll
        for (int ks = 0; ks < 4; ks++) {
            const uint4 f0 = q0[ks * 4 + qc];
            const uint4 f1 = q1[ks * 4 + qc];
            qh[ks][0] = f0.x; qh[ks][1] = f1.x; qh[ks][2] = f0.y; qh[ks][3] = f1.y;
            ql[ks][0] = f0.z; ql[ks][1] = f1.z; ql[ks][2] = f0.w; ql[ks][3] = f1.w;
        }
    }

    float oacc[8][4];
    #pragma unroll
    for (int tn = 0; tn < 8; tn++)
        #pragma unroll
        for (int e = 0; e < 4; e++) oacc[tn][e] = 0.f;
    float m0r = -1e30f, m1r = -1e30f, l0r = 0.f, l1r = 0.f;

    load_tile(0, 0);
    CP_COMMIT();

    #pragma unroll 1
    for (int it = 0; it < SEQ / 64; it++) {
        const int st = it & 1;
        if (it + 1 < SEQ / 64) {
            load_tile((it + 1) * 64, st ^ 1);
            CP_COMMIT();
            CP_WAIT1();
        } else {
            CP_WAIT0();
        }
        __syncthreads();

        const uint4*    Kb4  = (const uint4*)(s + st * STG_F);
        const uint32_t* Vh   = (const uint32_t*)(s + st * STG_F) + KV_OFF;
        const float*    ksqs = s + st * STG_F + KQ_OFF;

        float sacc[8][4];
        #pragma unroll
        for (int tn = 0; tn < 8; tn++)
            #pragma unroll
            for (int e = 0; e < 4; e++) sacc[tn][e] = 0.f;

        #pragma unroll
        for (int ks = 0; ks < 4; ks++) {
            #pragma unroll
            for (int tn = 0; tn < 8; tn++) {
                const uint4 wv = Kb4[(tn * 8 + qr) * KB4S + ks * 4 + qc];
                float* d = sacc[tn];
                mma_bf16(d, qh[ks][0], qh[ks][1], qh[ks][2], qh[ks][3], wv.x, wv.y);
                mma_bf16(d, qh[ks][0], qh[ks][1], qh[ks][2], qh[ks][3], wv.z, wv.w);
                mma_bf16(d, ql[ks][0], ql[ks][1], ql[ks][2], ql[ks][3], wv.x, wv.y);
            }
        }

        float mx0 = -1e30f, mx1 = -1e30f;
        const float2* ksq2 = (const float2*)ksqs;
        #pragma unroll
        for (int tn = 0; tn < 8; tn++) {
            const float2 kk = ksq2[tn * 4 + qc];
            sacc[tn][0] -= kk.x; sacc[tn][1] -= kk.y;
            sacc[tn][2] -= kk.x; sacc[tn][3] -= kk.y;
            mx0 = fmaxf(mx0, fmaxf(sacc[tn][0], sacc[tn][1]));
            mx1 = fmaxf(mx1, fmaxf(sacc[tn][2], sacc[tn][3]));
        }
        #pragma unroll
        for (int off = 1; off <= 2; off <<= 1) {
            mx0 = fmaxf(mx0, __shfl_xor_sync(0xffffffffu, mx0, off));
            mx1 = fmaxf(mx1, __shfl_xor_sync(0xffffffffu, mx1, off));
        }
        const float mn0 = fmaxf(m0r, mx0), mn1 = fmaxf(m1r, mx1);
        const float al0 = ex2f(m0r - mn0), al1 = ex2f(m1r - mn1);
        m0r = mn0; m1r = mn1;

        float rs0 = 0.f, rs1 = 0.f;
        #pragma unroll
        for (int tn = 0; tn < 8; tn++) {
            sacc[tn][0] = ex2f(sacc[tn][0] - mn0);
            sacc[tn][1] = ex2f(sacc[tn][1] - mn0);
            sacc[tn][2] = ex2f(sacc[tn][2] - mn1);
            sacc[tn][3] = ex2f(sacc[tn][3] - mn1);
            rs0 += sacc[tn][0] + sacc[tn][1];
            rs1 += sacc[tn][2] + sacc[tn][3];
            oacc[tn][0] *= al0; oacc[tn][1] *= al0;
            oacc[tn][2] *= al1; oacc[tn][3] *= al1;
        }
        l0r = l0r * al0 + rs0;
        l1r = l1r * al1 + rs1;

        #pragma unroll
        for (int ks = 0; ks < 4; ks++) {
            const uint32_t a0 = hpack(sacc[2*ks    ][0], sacc[2*ks    ][1]);
            const uint32_t a1 = hpack(sacc[2*ks    ][2], sacc[2*ks    ][3]);
            const uint32_t a2 = hpack(sacc[2*ks + 1][0], sacc[2*ks + 1][1]);
            const uint32_t a3 = hpack(sacc[2*ks + 1][2], sacc[2*ks + 1][3]);
            #pragma unroll
            for (int tn = 0; tn < 8; tn++) {
                const uint2 b01 =
                    *(const uint2*)&Vh[(ks * 4 + qc) * VST + (tn * 8 + qr) * 2];
                mma_f16(oacc[tn], a0, a1, a2, a3, b01.x, b01.y);
            }
        }
        __syncthreads();
    }

    #pragma unroll
    for (int off = 1; off <= 2; off <<= 1) {
        l0r += __shfl_xor_sync(0xffffffffu, l0r, off);
        l1r += __shfl_xor_sync(0xffffffffu, l1r, off);
    }
    const float inv0 = 1.f / l0r, inv1 = 1.f / l1r;
    const int b = bh >> 4, h = bh & 15;

    #pragma unroll
    for (int half = 0; half < 2; half++) {
        const int m = b * SEQ + s0 + wm + qr + half * 8;
        const int mblk = m >> 7, r = m & 127;
        const float inv = half ? inv1 : inv0;
        const int e0 = half * 2;
        #pragma unroll
        for (int tn = 0; tn < 8; tn += 2) {
            const int g = tn * 8 + 2 * qc;
            const int cglob = 2 * h + (g >> 5);
            const int sslot = ((g >> 4) & 1) * 4 + qc;
            float h0, l0, h1, l1, h2, l2, h3, l3;
            bsplit(oacc[tn    ][e0    ] * inv, h0, l0);
            bsplit(oacc[tn    ][e0 + 1] * inv, h1, l1);
            bsplit(oacc[tn + 1][e0    ] * inv, h2, l2);
            bsplit(oacc[tn + 1][e0 + 1] * inv, h3, l3);
            g_attp[((size_t)mblk * NCH + cglob) * 8 * 128 + sslot * 128 + r] =
                make_uint4(bpack(h0, h1), bpack(h2, h3), bpack(l0, l1), bpack(l2, l3));
        }
    }
}

// ---------------------------------------------------------------------------
extern "C" void kernel_launch(void* const* d_in, const int* in_sizes, int n_in,
                              void* d_out, int out_size) {
    (void)in_sizes; (void)n_in; (void)out_size;
    const float* x    = (const float*)d_in[0];
    const float* Wqkv = (const float*)d_in[1];
    const float* bqkv = (const float*)d_in[2];
    const float* Wo   = (const float*)d_in[3];
    const float* bo   = (const float*)d_in[4];
    float*       out  = (float*)d_out;

    uint4* xp;   cudaGetSymbolAddress((void**)&xp,   g_xp);
    uint4* attp; cudaGetSymbolAddress((void**)&attp, g_attp);
    uint4* wqp;  cudaGetSymbolAddress((void**)&wqp,  g_wqp);
    uint4* wop;  cudaGetSymbolAddress((void**)&wop,  g_wop);

    cudaFuncSetAttribute(bf16_gemm, cudaFuncAttributeMaxDynamicSharedMemorySize, GSMEM2);
    cudaFuncSetAttribute(flash_mma, cudaFuncAttributeMaxDynamicSharedMemorySize, FLASH_SMEM);

    pack_all<<<dim3(64, NCH), 256>>>(x, Wqkv, Wo);

    bf16_gemm<<<dim3(N_QKV/128, M_ROWS/64), 128, GSMEM2>>>(xp, wqp, bqkv, nullptr, 0);

    flash_mma<<<dim3(SEQ/128, NUM_B*NH), 256, FLASH_SMEM>>>();

    bf16_gemm<<<dim3(DIM/128, M_ROWS/64), 128, GSMEM2>>>(attp, wop, bo, out, 1);
}